// round 1
// baseline (speedup 1.0000x reference)
#include <cuda_runtime.h>

#define NPTS 1024
#define FDIM 40
#define EPSV 1e-7f
#define BJ 128

// Precomputed per-point partials of the layer-0 84->32 GEMMs.
// preA = feat @ W0[0:40]  + b0   (fc0, i-part, bias folded)
// preB = feat @ W0[40:80]        (fc0, j-part)
// preC = feat @ W1[0:40]  + b1   (fc1, i-part, bias folded)
// preD = feat @ W1[40:80]        (fc1, j-part)
__device__ float g_preA[NPTS * 32];
__device__ float g_preB[NPTS * 32];
__device__ float g_preC[NPTS * 32];
__device__ float g_preD[NPTS * 32];

__global__ void prep_kernel(const float* __restrict__ feat,
                            const float* __restrict__ w0, const float* __restrict__ b0,
                            const float* __restrict__ w1, const float* __restrict__ b1) {
    int p = blockIdx.x;        // point index
    int c = threadIdx.x;       // output channel 0..31
    float a = b0[c];
    float bb = 0.f;
    float cc = b1[c];
    float dd = 0.f;
#pragma unroll 8
    for (int k = 0; k < FDIM; k++) {
        float f = feat[p * FDIM + k];
        a  += f * w0[k * 32 + c];
        bb += f * w0[(FDIM + k) * 32 + c];
        cc += f * w1[k * 32 + c];
        dd += f * w1[(FDIM + k) * 32 + c];
    }
    g_preA[p * 32 + c] = a;
    g_preB[p * 32 + c] = bb;
    g_preC[p * 32 + c] = cc;
    g_preD[p * 32 + c] = dd;
}

// ---- shared memory layout (in floats) ----
#define OFF_W0P  0       // (4x32) ppf rows of l0_fc0_w
#define OFF_W1P  128     // (4x32) ppf rows of l0_fc1_w
#define OFF_W02  256     // (32x32) l0_fc2_w
#define OFF_B02  1280
#define OFF_W11  1312    // (32x32) l1_fc1_w
#define OFF_B11  2336
#define OFF_W12  2368    // (32x32) l1_fc2_w
#define OFF_B12  3392
#define OFF_W20  3424    // (32x16) l2_fc0_w
#define OFF_B20  3936
#define OFF_W21  3952    // (32x16) l2_fc1_w
#define OFF_B21  4464
#define OFF_W22  4480    // (16x16) l2_fc2_w
#define OFF_B22  4736
#define OFF_WFT  4752    // (66x16) final_w TRANSPOSED (row = out channel)
#define OFF_BF   5808    // 66
#define OFF_PREA 5874    // 32 (row i)
#define OFF_PREC 5906    // 32 (row i)
#define OFF_PCI  5938    // 3
#define OFF_NI   5941    // 3
#define OFF_OUT  5944    // 128*67 staging
#define SMEM_FLOATS (OFF_OUT + BJ * 67)
#define SMEM_BYTES  (SMEM_FLOATS * 4)

// acc[CC] += x[KK] @ W[KK][CC], W in smem (16B-aligned base, CC multiple of 4)
template <int KK, int CC>
__device__ __forceinline__ void gemm_acc(const float* sW, const float* x, float* acc) {
#pragma unroll
    for (int k = 0; k < KK; k++) {
        float xk = x[k];
        const float4* w4 = (const float4*)(sW + k * CC);
#pragma unroll
        for (int q = 0; q < CC / 4; q++) {
            float4 wv = w4[q];
            acc[4 * q + 0] += xk * wv.x;
            acc[4 * q + 1] += xk * wv.y;
            acc[4 * q + 2] += xk * wv.z;
            acc[4 * q + 3] += xk * wv.w;
        }
    }
}

__global__ __launch_bounds__(BJ) void ppf_main_kernel(
    const float* __restrict__ pc, const float* __restrict__ nrm,
    const float* __restrict__ dist,
    const float* __restrict__ w0,  const float* __restrict__ w1,
    const float* __restrict__ w02, const float* __restrict__ b02,
    const float* __restrict__ w11, const float* __restrict__ b11,
    const float* __restrict__ w12, const float* __restrict__ b12,
    const float* __restrict__ w20, const float* __restrict__ b20,
    const float* __restrict__ w21, const float* __restrict__ b21,
    const float* __restrict__ w22, const float* __restrict__ b22,
    const float* __restrict__ wf,  const float* __restrict__ bf,
    float* __restrict__ out)
{
    extern __shared__ float sm[];
    const int tid = threadIdx.x;
    const int i = blockIdx.y;
    const int j = blockIdx.x * BJ + tid;

    // ---- cooperative weight/state load ----
    for (int idx = tid; idx < 128; idx += BJ) {
        int r = idx >> 5, c = idx & 31;
        sm[OFF_W0P + idx] = w0[(80 + r) * 32 + c];
        sm[OFF_W1P + idx] = w1[(80 + r) * 32 + c];
    }
    for (int idx = tid; idx < 1024; idx += BJ) {
        sm[OFF_W02 + idx] = w02[idx];
        sm[OFF_W11 + idx] = w11[idx];
        sm[OFF_W12 + idx] = w12[idx];
    }
    for (int idx = tid; idx < 512; idx += BJ) {
        sm[OFF_W20 + idx] = w20[idx];
        sm[OFF_W21 + idx] = w21[idx];
    }
    for (int idx = tid; idx < 256; idx += BJ) sm[OFF_W22 + idx] = w22[idx];
    for (int idx = tid; idx < 1056; idx += BJ) {
        int c = idx >> 4, k = idx & 15;
        sm[OFF_WFT + idx] = wf[k * 66 + c];     // transpose
    }
    for (int idx = tid; idx < 66; idx += BJ) sm[OFF_BF + idx] = bf[idx];
    if (tid < 32) {
        sm[OFF_B02 + tid] = b02[tid];
        sm[OFF_B11 + tid] = b11[tid];
        sm[OFF_B12 + tid] = b12[tid];
        sm[OFF_PREA + tid] = g_preA[i * 32 + tid];
        sm[OFF_PREC + tid] = g_preC[i * 32 + tid];
    } else if (tid < 48) {
        int t = tid - 32;
        sm[OFF_B20 + t] = b20[t];
        sm[OFF_B21 + t] = b21[t];
        sm[OFF_B22 + t] = b22[t];
    } else if (tid < 51) {
        int t = tid - 48;
        sm[OFF_PCI + t] = pc[i * 3 + t];
        sm[OFF_NI + t]  = nrm[i * 3 + t];
    }
    __syncthreads();

    // ---- per-pair ppf ----
    const float pix = sm[OFF_PCI + 0], piy = sm[OFF_PCI + 1], piz = sm[OFF_PCI + 2];
    const float nix = sm[OFF_NI + 0],  niy = sm[OFF_NI + 1],  niz = sm[OFF_NI + 2];
    const float pjx = pc[j * 3 + 0], pjy = pc[j * 3 + 1], pjz = pc[j * 3 + 2];
    const float njx = nrm[j * 3 + 0], njy = nrm[j * 3 + 1], njz = nrm[j * 3 + 2];
    const float d = dist[(size_t)i * NPTS + j];
    const float inv = 1.f / (d + EPSV);
    const float xn0 = (pix - pjx) * inv;
    const float xn1 = (piy - pjy) * inv;
    const float xn2 = (piz - pjz) * inv;
    const float p0 = nix * xn0 + niy * xn1 + niz * xn2;
    const float p1 = njx * xn0 + njy * xn1 + njz * xn2;
    const float p2 = nix * njx + niy * njy + niz * njz;
    const float p3 = d;

    float A[32];   // x_res -> x1 -> x2
    float B[32];   // h -> h2

    // layer0: x_res = preA_i + preB_j + ppf @ W0p   (b0 folded into preA)
    {
        const float4* pB4 = (const float4*)(g_preB + (size_t)j * 32);
        const float4* pD4 = (const float4*)(g_preD + (size_t)j * 32);
#pragma unroll
        for (int q = 0; q < 8; q++) {
            float4 vb = __ldg(pB4 + q);
            A[4 * q + 0] = sm[OFF_PREA + 4 * q + 0] + vb.x;
            A[4 * q + 1] = sm[OFF_PREA + 4 * q + 1] + vb.y;
            A[4 * q + 2] = sm[OFF_PREA + 4 * q + 2] + vb.z;
            A[4 * q + 3] = sm[OFF_PREA + 4 * q + 3] + vb.w;
            float4 vd = __ldg(pD4 + q);
            B[4 * q + 0] = sm[OFF_PREC + 4 * q + 0] + vd.x;
            B[4 * q + 1] = sm[OFF_PREC + 4 * q + 1] + vd.y;
            B[4 * q + 2] = sm[OFF_PREC + 4 * q + 2] + vd.z;
            B[4 * q + 3] = sm[OFF_PREC + 4 * q + 3] + vd.w;
        }
#pragma unroll
        for (int c = 0; c < 32; c++) {
            A[c] += p0 * sm[OFF_W0P + c] + p1 * sm[OFF_W0P + 32 + c]
                  + p2 * sm[OFF_W0P + 64 + c] + p3 * sm[OFF_W0P + 96 + c];
            float hb = B[c] + p0 * sm[OFF_W1P + c] + p1 * sm[OFF_W1P + 32 + c]
                     + p2 * sm[OFF_W1P + 64 + c] + p3 * sm[OFF_W1P + 96 + c];
            B[c] = fmaxf(hb, 0.f);   // h = relu(...)
        }
    }

    // x1 = h @ l0_fc2 + b02 + x_res     (A := x1)
#pragma unroll
    for (int c = 0; c < 32; c++) A[c] += sm[OFF_B02 + c];
    gemm_acc<32, 32>(sm + OFF_W02, B, A);

    // h2 = relu(x1 @ l1_fc1 + b11)      (B := h2)
#pragma unroll
    for (int c = 0; c < 32; c++) B[c] = sm[OFF_B11 + c];
    gemm_acc<32, 32>(sm + OFF_W11, A, B);
#pragma unroll
    for (int c = 0; c < 32; c++) B[c] = fmaxf(B[c], 0.f);

    // x2 = h2 @ l1_fc2 + b12 + x1       (A := x2)
#pragma unroll
    for (int c = 0; c < 32; c++) A[c] += sm[OFF_B12 + c];
    gemm_acc<32, 32>(sm + OFF_W12, B, A);

    // layer2
    float R[16], H[16];
#pragma unroll
    for (int c = 0; c < 16; c++) { R[c] = sm[OFF_B20 + c]; H[c] = sm[OFF_B21 + c]; }
    gemm_acc<32, 16>(sm + OFF_W20, A, R);   // r = x2 @ fc0 + b
    gemm_acc<32, 16>(sm + OFF_W21, A, H);   // pre-relu
#pragma unroll
    for (int c = 0; c < 16; c++) H[c] = fmaxf(H[c], 0.f);
    float X3[16];
#pragma unroll
    for (int c = 0; c < 16; c++) X3[c] = sm[OFF_B22 + c] + R[c];
    gemm_acc<16, 16>(sm + OFF_W22, H, X3);  // x3 = h3 @ fc2 + b + r

    // final: out = x3 @ final_w + bf   (WFT transposed: row c = 16 weights)
    float* so = sm + OFF_OUT + tid * 67;
#pragma unroll 6
    for (int c = 0; c < 66; c++) {
        const float4* w4 = (const float4*)(sm + OFF_WFT + c * 16);
        float4 w0v = w4[0], w1v = w4[1], w2v = w4[2], w3v = w4[3];
        float s = sm[OFF_BF + c];
        s += X3[0] * w0v.x + X3[1] * w0v.y + X3[2] * w0v.z + X3[3] * w0v.w;
        s += X3[4] * w1v.x + X3[5] * w1v.y + X3[6] * w1v.z + X3[7] * w1v.w;
        s += X3[8] * w2v.x + X3[9] * w2v.y + X3[10] * w2v.z + X3[11] * w2v.w;
        s += X3[12] * w3v.x + X3[13] * w3v.y + X3[14] * w3v.z + X3[15] * w3v.w;
        so[c] = s;
    }
    __syncthreads();

    // coalesced flush of the 128*66 contiguous output floats of this block
    size_t base = ((size_t)i * NPTS + (size_t)blockIdx.x * BJ) * 66;
    for (int s = 0; s < 66; s++) {
        int idx = tid + s * BJ;
        int jj = idx / 66;
        int c = idx - jj * 66;
        out[base + idx] = sm[OFF_OUT + jj * 67 + c];
    }
}

extern "C" void kernel_launch(void* const* d_in, const int* in_sizes, int n_in,
                              void* d_out, int out_size) {
    const float* pc   = (const float*)d_in[0];
    const float* nrm  = (const float*)d_in[1];
    const float* dist = (const float*)d_in[2];
    const float* feat = (const float*)d_in[3];
    const float* w0   = (const float*)d_in[4];
    const float* b0   = (const float*)d_in[5];
    const float* w1   = (const float*)d_in[6];
    const float* b1   = (const float*)d_in[7];
    const float* w02  = (const float*)d_in[8];
    const float* b02  = (const float*)d_in[9];
    const float* w11  = (const float*)d_in[10];
    const float* b11  = (const float*)d_in[11];
    const float* w12  = (const float*)d_in[12];
    const float* b12  = (const float*)d_in[13];
    const float* w20  = (const float*)d_in[14];
    const float* b20  = (const float*)d_in[15];
    const float* w21  = (const float*)d_in[16];
    const float* b21  = (const float*)d_in[17];
    const float* w22  = (const float*)d_in[18];
    const float* b22  = (const float*)d_in[19];
    const float* wf   = (const float*)d_in[20];
    const float* bf   = (const float*)d_in[21];
    float* out = (float*)d_out;

    cudaFuncSetAttribute(ppf_main_kernel,
                         cudaFuncAttributeMaxDynamicSharedMemorySize, SMEM_BYTES);

    prep_kernel<<<NPTS, 32>>>(feat, w0, b0, w1, b1);

    dim3 grid(NPTS / BJ, NPTS);
    ppf_main_kernel<<<grid, BJ, SMEM_BYTES>>>(
        pc, nrm, dist, w0, w1,
        w02, b02, w11, b11, w12, b12,
        w20, b20, w21, b21, w22, b22,
        wf, bf, out);
}

// round 4
// speedup vs baseline: 1.4458x; 1.4458x over previous
#include <cuda_runtime.h>

#define NPTS 1024
#define FDIM 40
#define EPSV 1e-7f
#define BJ 128
#define PPB 256   // pairs per block (2 per thread)

typedef unsigned long long u64;

// Precomputed per-point partials of the layer-0 84->32 GEMMs.
__device__ float g_preA[NPTS * 32];  // feat @ W0[0:40] + b0   (i-part)
__device__ float g_preB[NPTS * 32];  // feat @ W0[40:80]       (j-part)
__device__ float g_preC[NPTS * 32];  // feat @ W1[0:40] + b1   (i-part)
__device__ float g_preD[NPTS * 32];  // feat @ W1[40:80]       (j-part)

__global__ void prep_kernel(const float* __restrict__ feat,
                            const float* __restrict__ w0, const float* __restrict__ b0,
                            const float* __restrict__ w1, const float* __restrict__ b1) {
    int p = blockIdx.x;
    int c = threadIdx.x;
    float a = b0[c];
    float bb = 0.f;
    float cc = b1[c];
    float dd = 0.f;
#pragma unroll 8
    for (int k = 0; k < FDIM; k++) {
        float f = feat[p * FDIM + k];
        a  += f * w0[k * 32 + c];
        bb += f * w0[(FDIM + k) * 32 + c];
        cc += f * w1[k * 32 + c];
        dd += f * w1[(FDIM + k) * 32 + c];
    }
    g_preA[p * 32 + c] = a;
    g_preB[p * 32 + c] = bb;
    g_preC[p * 32 + c] = cc;
    g_preD[p * 32 + c] = dd;
}

// ---- packed f32x2 helpers ----
__device__ __forceinline__ u64 pack2(float lo, float hi) {
    u64 r; asm("mov.b64 %0, {%1, %2};" : "=l"(r) : "f"(lo), "f"(hi)); return r;
}
__device__ __forceinline__ float2 unpack2(u64 v) {
    float2 f; asm("mov.b64 {%0, %1}, %2;" : "=f"(f.x), "=f"(f.y) : "l"(v)); return f;
}
__device__ __forceinline__ u64 fma2(u64 a, u64 b, u64 c) {
    u64 d; asm("fma.rn.f32x2 %0, %1, %2, %3;" : "=l"(d) : "l"(a), "l"(b), "l"(c)); return d;
}
__device__ __forceinline__ u64 mul2(u64 a, u64 b) {
    u64 d; asm("mul.rn.f32x2 %0, %1, %2;" : "=l"(d) : "l"(a), "l"(b)); return d;
}
__device__ __forceinline__ u64 add2(u64 a, u64 b) {
    u64 d; asm("add.rn.f32x2 %0, %1, %2;" : "=l"(d) : "l"(a), "l"(b)); return d;
}

// ---- shared memory layout (floats) ----
#define OFF_W0P  0       // 4x32
#define OFF_W1P  128     // 4x32
#define OFF_W02  256     // 32x32
#define OFF_W11  1280    // 32x32
#define OFF_W12  2304    // 32x32
#define OFF_W20  3328    // 32x16
#define OFF_W21  3840    // 32x16
#define OFF_W22  4352    // 16x16
#define OFF_WFT  4608    // 66x16 final_w transposed (row c = 16 k-weights)
#define OFF_B02  5664
#define OFF_B11  5696
#define OFF_B12  5728
#define OFF_B20  5760
#define OFF_B21  5776
#define OFF_B22  5792
#define OFF_BF   5808    // 66
#define OFF_PREA 5874    // 32 (row i)
#define OFF_PREC 5906    // 32 (row i)
#define OFF_PCI  5938    // 3
#define OFF_NI   5941    // 3
#define OFF_OUT  5944    // 256*67 staging
#define SMEM_FLOATS (OFF_OUT + PPB * 67)
#define SMEM_BYTES  (SMEM_FLOATS * 4)

// acc{0,1}[CC/2] += x{0,1} @ W (KK x CC), x given channel-packed (u64[KK/2]),
// optional relu applied to x when consumed. Weights shared across both pairs.
template <int KK, int CC, bool RELU>
__device__ __forceinline__ void gemm2_dual(const float* __restrict__ sW,
                                           const u64* __restrict__ x0,
                                           const u64* __restrict__ x1,
                                           u64* acc0, u64* acc1) {
#pragma unroll
    for (int k = 0; k < KK; k++) {
        float2 a = unpack2(x0[k >> 1]);
        float s0 = (k & 1) ? a.y : a.x;
        float2 b = unpack2(x1[k >> 1]);
        float s1 = (k & 1) ? b.y : b.x;
        if (RELU) { s0 = fmaxf(s0, 0.f); s1 = fmaxf(s1, 0.f); }
        u64 m0 = pack2(s0, s0);
        u64 m1 = pack2(s1, s1);
        const ulonglong2* w = (const ulonglong2*)(sW + k * CC);
#pragma unroll
        for (int q = 0; q < CC / 4; q++) {
            ulonglong2 wv = w[q];
            acc0[2 * q + 0] = fma2(wv.x, m0, acc0[2 * q + 0]);
            acc0[2 * q + 1] = fma2(wv.y, m0, acc0[2 * q + 1]);
            acc1[2 * q + 0] = fma2(wv.x, m1, acc1[2 * q + 0]);
            acc1[2 * q + 1] = fma2(wv.y, m1, acc1[2 * q + 1]);
        }
    }
}

__global__ __launch_bounds__(BJ) void ppf_main_kernel(
    const float* __restrict__ pc, const float* __restrict__ nrm,
    const float* __restrict__ dist,
    const float* __restrict__ w0,  const float* __restrict__ w1,
    const float* __restrict__ w02, const float* __restrict__ b02,
    const float* __restrict__ w11, const float* __restrict__ b11,
    const float* __restrict__ w12, const float* __restrict__ b12,
    const float* __restrict__ w20, const float* __restrict__ b20,
    const float* __restrict__ w21, const float* __restrict__ b21,
    const float* __restrict__ w22, const float* __restrict__ b22,
    const float* __restrict__ wf,  const float* __restrict__ bf,
    float* __restrict__ out)
{
    extern __shared__ float sm[];
    const int tid = threadIdx.x;
    const int i = blockIdx.y;
    const int j0 = blockIdx.x * PPB + tid;
    const int j1 = j0 + BJ;

    // ---- cooperative weight/state load ----
    for (int idx = tid; idx < 128; idx += BJ) {
        int r = idx >> 5, c = idx & 31;
        sm[OFF_W0P + idx] = w0[(80 + r) * 32 + c];
        sm[OFF_W1P + idx] = w1[(80 + r) * 32 + c];
    }
    for (int idx = tid; idx < 1024; idx += BJ) {
        sm[OFF_W02 + idx] = w02[idx];
        sm[OFF_W11 + idx] = w11[idx];
        sm[OFF_W12 + idx] = w12[idx];
    }
    for (int idx = tid; idx < 512; idx += BJ) {
        sm[OFF_W20 + idx] = w20[idx];
        sm[OFF_W21 + idx] = w21[idx];
    }
    for (int idx = tid; idx < 256; idx += BJ) sm[OFF_W22 + idx] = w22[idx];
    for (int idx = tid; idx < 1056; idx += BJ) {
        int c = idx >> 4, k = idx & 15;
        sm[OFF_WFT + idx] = wf[k * 66 + c];     // transpose
    }
    for (int idx = tid; idx < 66; idx += BJ) sm[OFF_BF + idx] = bf[idx];
    if (tid < 32) {
        sm[OFF_B02 + tid] = b02[tid];
        sm[OFF_B11 + tid] = b11[tid];
        sm[OFF_B12 + tid] = b12[tid];
        sm[OFF_PREA + tid] = g_preA[i * 32 + tid];
        sm[OFF_PREC + tid] = g_preC[i * 32 + tid];
    } else if (tid < 48) {
        int t = tid - 32;
        sm[OFF_B20 + t] = b20[t];
        sm[OFF_B21 + t] = b21[t];
        sm[OFF_B22 + t] = b22[t];
    } else if (tid < 51) {
        int t = tid - 48;
        sm[OFF_PCI + t] = pc[i * 3 + t];
        sm[OFF_NI + t]  = nrm[i * 3 + t];
    }
    __syncthreads();

    // ---- ppf for both pairs ----
    const float pix = sm[OFF_PCI + 0], piy = sm[OFF_PCI + 1], piz = sm[OFF_PCI + 2];
    const float nix = sm[OFF_NI + 0],  niy = sm[OFF_NI + 1],  niz = sm[OFF_NI + 2];

    float p0a, p1a, p2a, p3a, p0b, p1b, p2b, p3b;
    {
        float pjx = pc[j0 * 3 + 0], pjy = pc[j0 * 3 + 1], pjz = pc[j0 * 3 + 2];
        float njx = nrm[j0 * 3 + 0], njy = nrm[j0 * 3 + 1], njz = nrm[j0 * 3 + 2];
        float d = dist[(size_t)i * NPTS + j0];
        float inv = 1.f / (d + EPSV);
        float x0v = (pix - pjx) * inv, x1v = (piy - pjy) * inv, x2v = (piz - pjz) * inv;
        p0a = nix * x0v + niy * x1v + niz * x2v;
        p1a = njx * x0v + njy * x1v + njz * x2v;
        p2a = nix * njx + niy * njy + niz * njz;
        p3a = d;
    }
    {
        float pjx = pc[j1 * 3 + 0], pjy = pc[j1 * 3 + 1], pjz = pc[j1 * 3 + 2];
        float njx = nrm[j1 * 3 + 0], njy = nrm[j1 * 3 + 1], njz = nrm[j1 * 3 + 2];
        float d = dist[(size_t)i * NPTS + j1];
        float inv = 1.f / (d + EPSV);
        float x0v = (pix - pjx) * inv, x1v = (piy - pjy) * inv, x2v = (piz - pjz) * inv;
        p0b = nix * x0v + niy * x1v + niz * x2v;
        p1b = njx * x0v + njy * x1v + njz * x2v;
        p2b = nix * njx + niy * njy + niz * njz;
        p3b = d;
    }

    // channel-packed activation vectors (16 u64 = 32 channels each)
    u64 A0[16], A1[16], B0[16], B1[16];

    // layer0 linear parts: A = preA_i + preB_j ; B = preC_i + preD_j
    {
        const u64* pAi = (const u64*)(sm + OFF_PREA);
        const u64* pCi = (const u64*)(sm + OFF_PREC);
        const ulonglong2* pB0 = (const ulonglong2*)(g_preB + (size_t)j0 * 32);
        const ulonglong2* pB1 = (const ulonglong2*)(g_preB + (size_t)j1 * 32);
        const ulonglong2* pD0 = (const ulonglong2*)(g_preD + (size_t)j0 * 32);
        const ulonglong2* pD1 = (const ulonglong2*)(g_preD + (size_t)j1 * 32);
#pragma unroll
        for (int q = 0; q < 8; q++) {
            ulonglong2 vb0 = pB0[q], vb1 = pB1[q], vd0 = pD0[q], vd1 = pD1[q];
            A0[2 * q + 0] = add2(pAi[2 * q + 0], vb0.x);
            A0[2 * q + 1] = add2(pAi[2 * q + 1], vb0.y);
            A1[2 * q + 0] = add2(pAi[2 * q + 0], vb1.x);
            A1[2 * q + 1] = add2(pAi[2 * q + 1], vb1.y);
            B0[2 * q + 0] = add2(pCi[2 * q + 0], vd0.x);
            B0[2 * q + 1] = add2(pCi[2 * q + 1], vd0.y);
            B1[2 * q + 0] = add2(pCi[2 * q + 0], vd1.x);
            B1[2 * q + 1] = add2(pCi[2 * q + 1], vd1.y);
        }
    }

    // ppf @ W0p into A (x_res), ppf @ W1p into B (pre-relu h)
    {
        float pa[4] = {p0a, p1a, p2a, p3a};
        float pb[4] = {p0b, p1b, p2b, p3b};
#pragma unroll
        for (int r = 0; r < 4; r++) {
            u64 m0 = pack2(pa[r], pa[r]);
            u64 m1 = pack2(pb[r], pb[r]);
            const ulonglong2* w0r = (const ulonglong2*)(sm + OFF_W0P + r * 32);
            const ulonglong2* w1r = (const ulonglong2*)(sm + OFF_W1P + r * 32);
#pragma unroll
            for (int q = 0; q < 8; q++) {
                ulonglong2 wv = w0r[q];
                A0[2 * q + 0] = fma2(wv.x, m0, A0[2 * q + 0]);
                A0[2 * q + 1] = fma2(wv.y, m0, A0[2 * q + 1]);
                A1[2 * q + 0] = fma2(wv.x, m1, A1[2 * q + 0]);
                A1[2 * q + 1] = fma2(wv.y, m1, A1[2 * q + 1]);
                ulonglong2 uv = w1r[q];
                B0[2 * q + 0] = fma2(uv.x, m0, B0[2 * q + 0]);
                B0[2 * q + 1] = fma2(uv.y, m0, B0[2 * q + 1]);
                B1[2 * q + 0] = fma2(uv.x, m1, B1[2 * q + 0]);
                B1[2 * q + 1] = fma2(uv.y, m1, B1[2 * q + 1]);
            }
        }
    }

    // x1 = relu(B) @ W02 + b02 + x_res    (acc in A)
    {
        const u64* bb = (const u64*)(sm + OFF_B02);
#pragma unroll
        for (int q = 0; q < 16; q++) { A0[q] = add2(A0[q], bb[q]); A1[q] = add2(A1[q], bb[q]); }
    }
    gemm2_dual<32, 32, true>(sm + OFF_W02, B0, B1, A0, A1);

    // h2 = x1 @ W11 + b11 (relu deferred)   (acc in B)
    {
        const u64* bb = (const u64*)(sm + OFF_B11);
#pragma unroll
        for (int q = 0; q < 16; q++) { B0[q] = bb[q]; B1[q] = bb[q]; }
    }
    gemm2_dual<32, 32, false>(sm + OFF_W11, A0, A1, B0, B1);

    // x2 = relu(h2) @ W12 + b12 + x1        (acc in A)
    {
        const u64* bb = (const u64*)(sm + OFF_B12);
#pragma unroll
        for (int q = 0; q < 16; q++) { A0[q] = add2(A0[q], bb[q]); A1[q] = add2(A1[q], bb[q]); }
    }
    gemm2_dual<32, 32, true>(sm + OFF_W12, B0, B1, A0, A1);

    // layer2: R = x2 @ W20 + b20 ; H = x2 @ W21 + b21 (relu deferred)
    u64 R0[8], R1[8], H0[8], H1[8];
    {
        const u64* b20p = (const u64*)(sm + OFF_B20);
        const u64* b21p = (const u64*)(sm + OFF_B21);
#pragma unroll
        for (int q = 0; q < 8; q++) {
            R0[q] = b20p[q]; R1[q] = b20p[q];
            H0[q] = b21p[q]; H1[q] = b21p[q];
        }
    }
    gemm2_dual<32, 16, false>(sm + OFF_W20, A0, A1, R0, R1);
    gemm2_dual<32, 16, false>(sm + OFF_W21, A0, A1, H0, H1);

    // x3 = relu(H) @ W22 + b22 + R          (acc in R)
    {
        const u64* bb = (const u64*)(sm + OFF_B22);
#pragma unroll
        for (int q = 0; q < 8; q++) { R0[q] = add2(R0[q], bb[q]); R1[q] = add2(R1[q], bb[q]); }
    }
    gemm2_dual<16, 16, true>(sm + OFF_W22, H0, H1, R0, R1);

    // final: out_c = x3 . WFT[c] + bf[c]   (R is k-packed: R[q] = {x3_2q, x3_2q+1})
    float* so0 = sm + OFF_OUT + tid * 67;
    float* so1 = sm + OFF_OUT + (tid + BJ) * 67;
#pragma unroll 6
    for (int c = 0; c < 66; c++) {
        const ulonglong2* w = (const ulonglong2*)(sm + OFF_WFT + c * 16);
        ulonglong2 wa = w[0], wb = w[1], wc2 = w[2], wd = w[3];
        float bias = sm[OFF_BF + c];

        u64 sa = mul2(wa.x, R0[0]);
        sa = fma2(wa.y, R0[1], sa);
        sa = fma2(wb.x, R0[2], sa);
        sa = fma2(wb.y, R0[3], sa);
        u64 sb = mul2(wc2.x, R0[4]);
        sb = fma2(wc2.y, R0[5], sb);
        sb = fma2(wd.x, R0[6], sb);
        sb = fma2(wd.y, R0[7], sb);
        float2 f1 = unpack2(sa), f2 = unpack2(sb);
        so0[c] = bias + ((f1.x + f1.y) + (f2.x + f2.y));

        u64 ta = mul2(wa.x, R1[0]);
        ta = fma2(wa.y, R1[1], ta);
        ta = fma2(wb.x, R1[2], ta);
        ta = fma2(wb.y, R1[3], ta);
        u64 tb = mul2(wc2.x, R1[4]);
        tb = fma2(wc2.y, R1[5], tb);
        tb = fma2(wd.x, R1[6], tb);
        tb = fma2(wd.y, R1[7], tb);
        float2 g1 = unpack2(ta), g2 = unpack2(tb);
        so1[c] = bias + ((g1.x + g1.y) + (g2.x + g2.y));
    }
    __syncthreads();

    // coalesced flush: 256*66 contiguous output floats for this block
    size_t base = ((size_t)i * NPTS + (size_t)blockIdx.x * PPB) * 66;
#pragma unroll 4
    for (int s = 0; s < (PPB * 66) / BJ; s++) {
        int idx = tid + s * BJ;
        int jj = idx / 66;
        int c = idx - jj * 66;
        out[base + idx] = sm[OFF_OUT + jj * 67 + c];
    }
}

extern "C" void kernel_launch(void* const* d_in, const int* in_sizes, int n_in,
                              void* d_out, int out_size) {
    const float* pc   = (const float*)d_in[0];
    const float* nrm  = (const float*)d_in[1];
    const float* dist = (const float*)d_in[2];
    const float* feat = (const float*)d_in[3];
    const float* w0   = (const float*)d_in[4];
    const float* b0   = (const float*)d_in[5];
    const float* w1   = (const float*)d_in[6];
    const float* b1   = (const float*)d_in[7];
    const float* w02  = (const float*)d_in[8];
    const float* b02  = (const float*)d_in[9];
    const float* w11  = (const float*)d_in[10];
    const float* b11  = (const float*)d_in[11];
    const float* w12  = (const float*)d_in[12];
    const float* b12  = (const float*)d_in[13];
    const float* w20  = (const float*)d_in[14];
    const float* b20  = (const float*)d_in[15];
    const float* w21  = (const float*)d_in[16];
    const float* b21  = (const float*)d_in[17];
    const float* w22  = (const float*)d_in[18];
    const float* b22  = (const float*)d_in[19];
    const float* wf   = (const float*)d_in[20];
    const float* bf   = (const float*)d_in[21];
    float* out = (float*)d_out;

    cudaFuncSetAttribute(ppf_main_kernel,
                         cudaFuncAttributeMaxDynamicSharedMemorySize, SMEM_BYTES);

    prep_kernel<<<NPTS, 32>>>(feat, w0, b0, w1, b1);

    dim3 grid(NPTS / PPB, NPTS);
    ppf_main_kernel<<<grid, BJ, SMEM_BYTES>>>(
        pc, nrm, dist, w0, w1,
        w02, b02, w11, b11, w12, b12,
        w20, b20, w21, b21, w22, b22,
        wf, bf, out);
}

// round 5
// speedup vs baseline: 1.4471x; 1.0009x over previous
#include <cuda_runtime.h>

#define NPTS 1024
#define FDIM 40
#define EPSV 1e-7f
#define BJ 128
#define PPB 256   // pairs per block (2 per thread)

typedef unsigned long long u64;

// Precomputed per-point partials of the layer-0 84->32 GEMMs.
__device__ float g_preA[NPTS * 32];  // feat @ W0[0:40] + b0   (i-part)
__device__ float g_preB[NPTS * 32];  // feat @ W0[40:80]       (j-part)
__device__ float g_preC[NPTS * 32];  // feat @ W1[0:40] + b1   (i-part)
__device__ float g_preD[NPTS * 32];  // feat @ W1[40:80]       (j-part)

__global__ void prep_kernel(const float* __restrict__ feat,
                            const float* __restrict__ w0, const float* __restrict__ b0,
                            const float* __restrict__ w1, const float* __restrict__ b1) {
    int p = blockIdx.x;
    int c = threadIdx.x;
    float a = b0[c];
    float bb = 0.f;
    float cc = b1[c];
    float dd = 0.f;
#pragma unroll 8
    for (int k = 0; k < FDIM; k++) {
        float f = feat[p * FDIM + k];
        a  += f * w0[k * 32 + c];
        bb += f * w0[(FDIM + k) * 32 + c];
        cc += f * w1[k * 32 + c];
        dd += f * w1[(FDIM + k) * 32 + c];
    }
    g_preA[p * 32 + c] = a;
    g_preB[p * 32 + c] = bb;
    g_preC[p * 32 + c] = cc;
    g_preD[p * 32 + c] = dd;
}

// ---- packed f32x2 helpers ----
__device__ __forceinline__ u64 pack2(float lo, float hi) {
    u64 r; asm("mov.b64 %0, {%1, %2};" : "=l"(r) : "f"(lo), "f"(hi)); return r;
}
__device__ __forceinline__ float2 unpack2(u64 v) {
    float2 f; asm("mov.b64 {%0, %1}, %2;" : "=f"(f.x), "=f"(f.y) : "l"(v)); return f;
}
__device__ __forceinline__ u64 fma2(u64 a, u64 b, u64 c) {
    u64 d; asm("fma.rn.f32x2 %0, %1, %2, %3;" : "=l"(d) : "l"(a), "l"(b), "l"(c)); return d;
}
__device__ __forceinline__ u64 mul2(u64 a, u64 b) {
    u64 d; asm("mul.rn.f32x2 %0, %1, %2;" : "=l"(d) : "l"(a), "l"(b)); return d;
}
__device__ __forceinline__ u64 add2(u64 a, u64 b) {
    u64 d; asm("add.rn.f32x2 %0, %1, %2;" : "=l"(d) : "l"(a), "l"(b)); return d;
}

// ---- shared memory layout (floats) ----
#define OFF_W0P  0       // 4x32
#define OFF_W1P  128     // 4x32
#define OFF_W02  256     // 32x32
#define OFF_W11  1280    // 32x32
#define OFF_W12  2304    // 32x32
#define OFF_W20  3328    // 32x16
#define OFF_W21  3840    // 32x16
#define OFF_W22  4352    // 16x16
#define OFF_WFT  4608    // 66x16 final_w transposed (row c = 16 k-weights)
#define OFF_B02  5664
#define OFF_B11  5696
#define OFF_B12  5728
#define OFF_B20  5760
#define OFF_B21  5776
#define OFF_B22  5792
#define OFF_BF   5808    // 66
#define OFF_PREA 5874    // 32 (row i)
#define OFF_PREC 5906    // 32 (row i)
#define OFF_PCI  5938    // 3
#define OFF_NI   5941    // 3
#define OFF_OUT  5944    // 256*67 staging
#define SMEM_FLOATS (OFF_OUT + PPB * 67)
#define SMEM_BYTES  (SMEM_FLOATS * 4)

// acc{0,1}[CC/2] += x{0,1} @ W (KK x CC), x given channel-packed (u64[KK/2]),
// optional relu applied to x when consumed. Weights shared across both pairs.
template <int KK, int CC, bool RELU>
__device__ __forceinline__ void gemm2_dual(const float* __restrict__ sW,
                                           const u64* __restrict__ x0,
                                           const u64* __restrict__ x1,
                                           u64* acc0, u64* acc1) {
#pragma unroll
    for (int k = 0; k < KK; k++) {
        float2 a = unpack2(x0[k >> 1]);
        float s0 = (k & 1) ? a.y : a.x;
        float2 b = unpack2(x1[k >> 1]);
        float s1 = (k & 1) ? b.y : b.x;
        if (RELU) { s0 = fmaxf(s0, 0.f); s1 = fmaxf(s1, 0.f); }
        u64 m0 = pack2(s0, s0);
        u64 m1 = pack2(s1, s1);
        const ulonglong2* w = (const ulonglong2*)(sW + k * CC);
#pragma unroll
        for (int q = 0; q < CC / 4; q++) {
            ulonglong2 wv = w[q];
            acc0[2 * q + 0] = fma2(wv.x, m0, acc0[2 * q + 0]);
            acc0[2 * q + 1] = fma2(wv.y, m0, acc0[2 * q + 1]);
            acc1[2 * q + 0] = fma2(wv.x, m1, acc1[2 * q + 0]);
            acc1[2 * q + 1] = fma2(wv.y, m1, acc1[2 * q + 1]);
        }
    }
}

__global__ __launch_bounds__(BJ) void ppf_main_kernel(
    const float* __restrict__ pc, const float* __restrict__ nrm,
    const float* __restrict__ dist,
    const float* __restrict__ w0,  const float* __restrict__ w1,
    const float* __restrict__ w02, const float* __restrict__ b02,
    const float* __restrict__ w11, const float* __restrict__ b11,
    const float* __restrict__ w12, const float* __restrict__ b12,
    const float* __restrict__ w20, const float* __restrict__ b20,
    const float* __restrict__ w21, const float* __restrict__ b21,
    const float* __restrict__ w22, const float* __restrict__ b22,
    const float* __restrict__ wf,  const float* __restrict__ bf,
    float* __restrict__ out)
{
    extern __shared__ float sm[];
    const int tid = threadIdx.x;
    const int i = blockIdx.y;
    const int j0 = blockIdx.x * PPB + tid;
    const int j1 = j0 + BJ;

    // ---- cooperative weight/state load ----
    for (int idx = tid; idx < 128; idx += BJ) {
        int r = idx >> 5, c = idx & 31;
        sm[OFF_W0P + idx] = w0[(80 + r) * 32 + c];
        sm[OFF_W1P + idx] = w1[(80 + r) * 32 + c];
    }
    for (int idx = tid; idx < 1024; idx += BJ) {
        sm[OFF_W02 + idx] = w02[idx];
        sm[OFF_W11 + idx] = w11[idx];
        sm[OFF_W12 + idx] = w12[idx];
    }
    for (int idx = tid; idx < 512; idx += BJ) {
        sm[OFF_W20 + idx] = w20[idx];
        sm[OFF_W21 + idx] = w21[idx];
    }
    for (int idx = tid; idx < 256; idx += BJ) sm[OFF_W22 + idx] = w22[idx];
    for (int idx = tid; idx < 1056; idx += BJ) {
        int c = idx >> 4, k = idx & 15;
        sm[OFF_WFT + idx] = wf[k * 66 + c];     // transpose
    }
    for (int idx = tid; idx < 66; idx += BJ) sm[OFF_BF + idx] = bf[idx];
    if (tid < 32) {
        sm[OFF_B02 + tid] = b02[tid];
        sm[OFF_B11 + tid] = b11[tid];
        sm[OFF_B12 + tid] = b12[tid];
        sm[OFF_PREA + tid] = g_preA[i * 32 + tid];
        sm[OFF_PREC + tid] = g_preC[i * 32 + tid];
    } else if (tid < 48) {
        int t = tid - 32;
        sm[OFF_B20 + t] = b20[t];
        sm[OFF_B21 + t] = b21[t];
        sm[OFF_B22 + t] = b22[t];
    } else if (tid < 51) {
        int t = tid - 48;
        sm[OFF_PCI + t] = pc[i * 3 + t];
        sm[OFF_NI + t]  = nrm[i * 3 + t];
    }
    __syncthreads();

    // ---- ppf for both pairs ----
    const float pix = sm[OFF_PCI + 0], piy = sm[OFF_PCI + 1], piz = sm[OFF_PCI + 2];
    const float nix = sm[OFF_NI + 0],  niy = sm[OFF_NI + 1],  niz = sm[OFF_NI + 2];

    float p0a, p1a, p2a, p3a, p0b, p1b, p2b, p3b;
    {
        float pjx = pc[j0 * 3 + 0], pjy = pc[j0 * 3 + 1], pjz = pc[j0 * 3 + 2];
        float njx = nrm[j0 * 3 + 0], njy = nrm[j0 * 3 + 1], njz = nrm[j0 * 3 + 2];
        float d = dist[(size_t)i * NPTS + j0];
        float inv = 1.f / (d + EPSV);
        float x0v = (pix - pjx) * inv, x1v = (piy - pjy) * inv, x2v = (piz - pjz) * inv;
        p0a = nix * x0v + niy * x1v + niz * x2v;
        p1a = njx * x0v + njy * x1v + njz * x2v;
        p2a = nix * njx + niy * njy + niz * njz;
        p3a = d;
    }
    {
        float pjx = pc[j1 * 3 + 0], pjy = pc[j1 * 3 + 1], pjz = pc[j1 * 3 + 2];
        float njx = nrm[j1 * 3 + 0], njy = nrm[j1 * 3 + 1], njz = nrm[j1 * 3 + 2];
        float d = dist[(size_t)i * NPTS + j1];
        float inv = 1.f / (d + EPSV);
        float x0v = (pix - pjx) * inv, x1v = (piy - pjy) * inv, x2v = (piz - pjz) * inv;
        p0b = nix * x0v + niy * x1v + niz * x2v;
        p1b = njx * x0v + njy * x1v + njz * x2v;
        p2b = nix * njx + niy * njy + niz * njz;
        p3b = d;
    }

    // channel-packed activation vectors (16 u64 = 32 channels each)
    u64 A0[16], A1[16], B0[16], B1[16];

    // layer0 linear parts: A = preA_i + preB_j ; B = preC_i + preD_j
    {
        const u64* pAi = (const u64*)(sm + OFF_PREA);
        const u64* pCi = (const u64*)(sm + OFF_PREC);
        const ulonglong2* pB0 = (const ulonglong2*)(g_preB + (size_t)j0 * 32);
        const ulonglong2* pB1 = (const ulonglong2*)(g_preB + (size_t)j1 * 32);
        const ulonglong2* pD0 = (const ulonglong2*)(g_preD + (size_t)j0 * 32);
        const ulonglong2* pD1 = (const ulonglong2*)(g_preD + (size_t)j1 * 32);
#pragma unroll
        for (int q = 0; q < 8; q++) {
            ulonglong2 vb0 = pB0[q], vb1 = pB1[q], vd0 = pD0[q], vd1 = pD1[q];
            A0[2 * q + 0] = add2(pAi[2 * q + 0], vb0.x);
            A0[2 * q + 1] = add2(pAi[2 * q + 1], vb0.y);
            A1[2 * q + 0] = add2(pAi[2 * q + 0], vb1.x);
            A1[2 * q + 1] = add2(pAi[2 * q + 1], vb1.y);
            B0[2 * q + 0] = add2(pCi[2 * q + 0], vd0.x);
            B0[2 * q + 1] = add2(pCi[2 * q + 1], vd0.y);
            B1[2 * q + 0] = add2(pCi[2 * q + 0], vd1.x);
            B1[2 * q + 1] = add2(pCi[2 * q + 1], vd1.y);
        }
    }

    // ppf @ W0p into A (x_res), ppf @ W1p into B (pre-relu h)
    {
        float pa[4] = {p0a, p1a, p2a, p3a};
        float pb[4] = {p0b, p1b, p2b, p3b};
#pragma unroll
        for (int r = 0; r < 4; r++) {
            u64 m0 = pack2(pa[r], pa[r]);
            u64 m1 = pack2(pb[r], pb[r]);
            const ulonglong2* w0r = (const ulonglong2*)(sm + OFF_W0P + r * 32);
            const ulonglong2* w1r = (const ulonglong2*)(sm + OFF_W1P + r * 32);
#pragma unroll
            for (int q = 0; q < 8; q++) {
                ulonglong2 wv = w0r[q];
                A0[2 * q + 0] = fma2(wv.x, m0, A0[2 * q + 0]);
                A0[2 * q + 1] = fma2(wv.y, m0, A0[2 * q + 1]);
                A1[2 * q + 0] = fma2(wv.x, m1, A1[2 * q + 0]);
                A1[2 * q + 1] = fma2(wv.y, m1, A1[2 * q + 1]);
                ulonglong2 uv = w1r[q];
                B0[2 * q + 0] = fma2(uv.x, m0, B0[2 * q + 0]);
                B0[2 * q + 1] = fma2(uv.y, m0, B0[2 * q + 1]);
                B1[2 * q + 0] = fma2(uv.x, m1, B1[2 * q + 0]);
                B1[2 * q + 1] = fma2(uv.y, m1, B1[2 * q + 1]);
            }
        }
    }

    // x1 = relu(B) @ W02 + b02 + x_res    (acc in A)
    {
        const u64* bb = (const u64*)(sm + OFF_B02);
#pragma unroll
        for (int q = 0; q < 16; q++) { A0[q] = add2(A0[q], bb[q]); A1[q] = add2(A1[q], bb[q]); }
    }
    gemm2_dual<32, 32, true>(sm + OFF_W02, B0, B1, A0, A1);

    // h2 = x1 @ W11 + b11 (relu deferred)   (acc in B)
    {
        const u64* bb = (const u64*)(sm + OFF_B11);
#pragma unroll
        for (int q = 0; q < 16; q++) { B0[q] = bb[q]; B1[q] = bb[q]; }
    }
    gemm2_dual<32, 32, false>(sm + OFF_W11, A0, A1, B0, B1);

    // x2 = relu(h2) @ W12 + b12 + x1        (acc in A)
    {
        const u64* bb = (const u64*)(sm + OFF_B12);
#pragma unroll
        for (int q = 0; q < 16; q++) { A0[q] = add2(A0[q], bb[q]); A1[q] = add2(A1[q], bb[q]); }
    }
    gemm2_dual<32, 32, true>(sm + OFF_W12, B0, B1, A0, A1);

    // layer2: R = x2 @ W20 + b20 ; H = x2 @ W21 + b21 (relu deferred)
    u64 R0[8], R1[8], H0[8], H1[8];
    {
        const u64* b20p = (const u64*)(sm + OFF_B20);
        const u64* b21p = (const u64*)(sm + OFF_B21);
#pragma unroll
        for (int q = 0; q < 8; q++) {
            R0[q] = b20p[q]; R1[q] = b20p[q];
            H0[q] = b21p[q]; H1[q] = b21p[q];
        }
    }
    gemm2_dual<32, 16, false>(sm + OFF_W20, A0, A1, R0, R1);
    gemm2_dual<32, 16, false>(sm + OFF_W21, A0, A1, H0, H1);

    // x3 = relu(H) @ W22 + b22 + R          (acc in R)
    {
        const u64* bb = (const u64*)(sm + OFF_B22);
#pragma unroll
        for (int q = 0; q < 8; q++) { R0[q] = add2(R0[q], bb[q]); R1[q] = add2(R1[q], bb[q]); }
    }
    gemm2_dual<16, 16, true>(sm + OFF_W22, H0, H1, R0, R1);

    // final: out_c = x3 . WFT[c] + bf[c]   (R is k-packed: R[q] = {x3_2q, x3_2q+1})
    float* so0 = sm + OFF_OUT + tid * 67;
    float* so1 = sm + OFF_OUT + (tid + BJ) * 67;
#pragma unroll 6
    for (int c = 0; c < 66; c++) {
        const ulonglong2* w = (const ulonglong2*)(sm + OFF_WFT + c * 16);
        ulonglong2 wa = w[0], wb = w[1], wc2 = w[2], wd = w[3];
        float bias = sm[OFF_BF + c];

        u64 sa = mul2(wa.x, R0[0]);
        sa = fma2(wa.y, R0[1], sa);
        sa = fma2(wb.x, R0[2], sa);
        sa = fma2(wb.y, R0[3], sa);
        u64 sb = mul2(wc2.x, R0[4]);
        sb = fma2(wc2.y, R0[5], sb);
        sb = fma2(wd.x, R0[6], sb);
        sb = fma2(wd.y, R0[7], sb);
        float2 f1 = unpack2(sa), f2 = unpack2(sb);
        so0[c] = bias + ((f1.x + f1.y) + (f2.x + f2.y));

        u64 ta = mul2(wa.x, R1[0]);
        ta = fma2(wa.y, R1[1], ta);
        ta = fma2(wb.x, R1[2], ta);
        ta = fma2(wb.y, R1[3], ta);
        u64 tb = mul2(wc2.x, R1[4]);
        tb = fma2(wc2.y, R1[5], tb);
        tb = fma2(wd.x, R1[6], tb);
        tb = fma2(wd.y, R1[7], tb);
        float2 g1 = unpack2(ta), g2 = unpack2(tb);
        so1[c] = bias + ((g1.x + g1.y) + (g2.x + g2.y));
    }
    __syncthreads();

    // coalesced flush: 256*66 contiguous output floats for this block
    size_t base = ((size_t)i * NPTS + (size_t)blockIdx.x * PPB) * 66;
#pragma unroll 4
    for (int s = 0; s < (PPB * 66) / BJ; s++) {
        int idx = tid + s * BJ;
        int jj = idx / 66;
        int c = idx - jj * 66;
        out[base + idx] = sm[OFF_OUT + jj * 67 + c];
    }
}

extern "C" void kernel_launch(void* const* d_in, const int* in_sizes, int n_in,
                              void* d_out, int out_size) {
    const float* pc   = (const float*)d_in[0];
    const float* nrm  = (const float*)d_in[1];
    const float* dist = (const float*)d_in[2];
    const float* feat = (const float*)d_in[3];
    const float* w0   = (const float*)d_in[4];
    const float* b0   = (const float*)d_in[5];
    const float* w1   = (const float*)d_in[6];
    const float* b1   = (const float*)d_in[7];
    const float* w02  = (const float*)d_in[8];
    const float* b02  = (const float*)d_in[9];
    const float* w11  = (const float*)d_in[10];
    const float* b11  = (const float*)d_in[11];
    const float* w12  = (const float*)d_in[12];
    const float* b12  = (const float*)d_in[13];
    const float* w20  = (const float*)d_in[14];
    const float* b20  = (const float*)d_in[15];
    const float* w21  = (const float*)d_in[16];
    const float* b21  = (const float*)d_in[17];
    const float* w22  = (const float*)d_in[18];
    const float* b22  = (const float*)d_in[19];
    const float* wf   = (const float*)d_in[20];
    const float* bf   = (const float*)d_in[21];
    float* out = (float*)d_out;

    cudaFuncSetAttribute(ppf_main_kernel,
                         cudaFuncAttributeMaxDynamicSharedMemorySize, SMEM_BYTES);

    prep_kernel<<<NPTS, 32>>>(feat, w0, b0, w1, b1);

    dim3 grid(NPTS / PPB, NPTS);
    ppf_main_kernel<<<grid, BJ, SMEM_BYTES>>>(
        pc, nrm, dist, w0, w1,
        w02, b02, w11, b11, w12, b12,
        w20, b20, w21, b21, w22, b22,
        wf, bf, out);
}

// round 8
// speedup vs baseline: 1.7831x; 1.2322x over previous
#include <cuda_runtime.h>
#include <cuda_bf16.h>
#include <stdint.h>

#define NPTS 1024
#define FDIM 40
#define EPSV 1e-7f
#define NTHR 128

// ---------------- device globals ----------------
__device__ float g_preA[NPTS*32], g_preB[NPTS*32], g_preC[NPTS*32], g_preD[NPTS*32];
// dense [N][K] bf16 hi/lo weight splits
__device__ __nv_bfloat16 g_w02h[1024], g_w02l[1024], g_w11h[1024], g_w11l[1024];
__device__ __nv_bfloat16 g_w12h[1024], g_w12l[1024], g_w45h[1024], g_w45l[1024];
__device__ __nv_bfloat16 g_w22h[256],  g_w22l[256],  g_wfh[1152],  g_wfl[1152];

__global__ void prep_pre(const float* __restrict__ feat,
                         const float* __restrict__ w0, const float* __restrict__ b0,
                         const float* __restrict__ w1, const float* __restrict__ b1) {
    int p = blockIdx.x, c = threadIdx.x;
    float a = b0[c], bb = 0.f, cc = b1[c], dd = 0.f;
#pragma unroll 8
    for (int k = 0; k < FDIM; k++) {
        float f = feat[p*FDIM+k];
        a  += f*w0[k*32+c];  bb += f*w0[(FDIM+k)*32+c];
        cc += f*w1[k*32+c];  dd += f*w1[(FDIM+k)*32+c];
    }
    g_preA[p*32+c]=a; g_preB[p*32+c]=bb; g_preC[p*32+c]=cc; g_preD[p*32+c]=dd;
}

__device__ __forceinline__ void bsplit(float v, __nv_bfloat16* H, __nv_bfloat16* L, int i) {
    __nv_bfloat16 h = __float2bfloat16(v);
    H[i] = h; L[i] = __float2bfloat16(v - __bfloat162float(h));
}

__global__ void prep_split(const float* __restrict__ w02, const float* __restrict__ w11,
                           const float* __restrict__ w12, const float* __restrict__ w20,
                           const float* __restrict__ w21, const float* __restrict__ w22,
                           const float* __restrict__ wf) {
    int t = threadIdx.x;
    for (int i = t; i < 1024; i += blockDim.x) {
        int n = i >> 5, k = i & 31;
        bsplit(w02[k*32+n], g_w02h, g_w02l, i);
        bsplit(w11[k*32+n], g_w11h, g_w11l, i);
        bsplit(w12[k*32+n], g_w12h, g_w12l, i);
        float v45 = (n < 16) ? w20[k*16+n] : w21[k*16+(n-16)];
        bsplit(v45, g_w45h, g_w45l, i);
    }
    for (int i = t; i < 256; i += blockDim.x) {
        int n = i >> 4, k = i & 15;
        bsplit(w22[k*16+n], g_w22h, g_w22l, i);
    }
    for (int i = t; i < 1152; i += blockDim.x) {
        int n = i >> 4, k = i & 15;
        bsplit(n < 66 ? wf[k*66+n] : 0.f, g_wfh, g_wfl, i);
    }
}

// ---------------- mma helpers ----------------
__device__ __forceinline__ uint32_t cvt2bf(float hi, float lo) {
    uint32_t r; asm("cvt.rn.bf16x2.f32 %0, %1, %2;" : "=r"(r) : "f"(hi), "f"(lo)); return r;
}
__device__ __forceinline__ uint32_t lo_resid(uint32_t h, float f0, float f1) {
    float h0 = __uint_as_float(h << 16);
    float h1 = __uint_as_float(h & 0xffff0000u);
    return cvt2bf(f1 - h1, f0 - h0);
}
__device__ __forceinline__ void mma16816(float* c, const uint32_t* a, const uint32_t* b) {
    asm volatile("mma.sync.aligned.m16n8k16.row.col.f32.bf16.bf16.f32 "
        "{%0,%1,%2,%3}, {%4,%5,%6,%7}, {%8,%9}, {%0,%1,%2,%3};"
        : "+f"(c[0]), "+f"(c[1]), "+f"(c[2]), "+f"(c[3])
        : "r"(a[0]), "r"(a[1]), "r"(a[2]), "r"(a[3]), "r"(b[0]), "r"(b[1]));
}
// c[NT][4] = (Ah+Al)@(Wh+Wl) (3-term), A in frags, W[N][K] bf16 in smem (pitch P bf16)
template<int NT, int KS, int P>
__device__ __forceinline__ void gemm_mma(float c[][4],
        const uint32_t ah[][4], const uint32_t al[][4],
        const char* wh, const char* wl, int lane) {
#pragma unroll
    for (int nt = 0; nt < NT; nt++) { c[nt][0]=0.f; c[nt][1]=0.f; c[nt][2]=0.f; c[nt][3]=0.f; }
    const int n0 = lane >> 2, k0 = (lane & 3) * 2;
#pragma unroll
    for (int ks = 0; ks < KS; ks++) {
#pragma unroll
        for (int nt = 0; nt < NT; nt++) {
            const char* ph = wh + ((nt*8 + n0) * P + ks*16 + k0) * 2;
            uint32_t bh[2] = { *(const uint32_t*)ph, *(const uint32_t*)(ph + 16) };
            mma16816(c[nt], ah[ks], bh);
            mma16816(c[nt], al[ks], bh);
            const char* pl = wl + ((nt*8 + n0) * P + ks*16 + k0) * 2;
            uint32_t bl[2] = { *(const uint32_t*)pl, *(const uint32_t*)(pl + 16) };
            mma16816(c[nt], ah[ks], bl);
        }
    }
}
// build one k16 a-frag pair (hi/lo) from two adjacent n8 c-frags (fragment layouts match)
__device__ __forceinline__ void cvt_frag(uint32_t* ah, uint32_t* al, const float* cA, const float* cB) {
    ah[0] = cvt2bf(cA[1], cA[0]); al[0] = lo_resid(ah[0], cA[0], cA[1]);
    ah[1] = cvt2bf(cA[3], cA[2]); al[1] = lo_resid(ah[1], cA[2], cA[3]);
    ah[2] = cvt2bf(cB[1], cB[0]); al[2] = lo_resid(ah[2], cB[0], cB[1]);
    ah[3] = cvt2bf(cB[3], cB[2]); al[3] = lo_resid(ah[3], cB[2], cB[3]);
}

// ---------------- smem layout (bytes) ----------------
#define P32 40
#define P16 24
#define O_W02H 0
#define O_W02L 2560
#define O_W11H 5120
#define O_W11L 7680
#define O_W12H 10240
#define O_W12L 12800
#define O_W45H 15360
#define O_W45L 17920
#define O_W22H 20480
#define O_W22L 21248
#define O_WFH  22016
#define O_WFL  25472
#define O_SC   28928   /* f32[544] */
#define BI_B02 0
#define BI_B11 32
#define BI_B12 64
#define BI_B45 96
#define BI_B22 128
#define BI_BF  144
#define SC_W0P 216
#define SC_W1P 344
#define SC_PREA 472
#define SC_PREC 504
#define SC_PCNI 536
#define O_HHI  31104   /* u32[128*17] */
#define O_HLO  39808
#define O_XR   48512   /* f32[128*33] */
#define O_OUT  65408   /* f32[4 warps][16*67] */
#define SMEM_BYTES (65408 + 4*16*67*4)

__global__ __launch_bounds__(NTHR) void ppf_mma_kernel(
    const float* __restrict__ pc, const float* __restrict__ nrm,
    const float* __restrict__ dist,
    const float* __restrict__ w0,  const float* __restrict__ w1,
    const float* __restrict__ b02, const float* __restrict__ b11, const float* __restrict__ b12,
    const float* __restrict__ b20, const float* __restrict__ b21, const float* __restrict__ b22,
    const float* __restrict__ bf,  float* __restrict__ out)
{
    extern __shared__ char smc[];
    float* BS = (float*)(smc + O_SC);
    const int tid = threadIdx.x, lane = tid & 31, w = tid >> 5;
    const int i = blockIdx.y, bx = blockIdx.x;

    // ---- stage weights (dense [N][K] -> pitched) ----
    for (int idx = tid; idx < 1024; idx += NTHR) {
        int n = idx >> 5, k = idx & 31, o = n * P32 + k;
        ((__nv_bfloat16*)(smc + O_W02H))[o] = g_w02h[idx];
        ((__nv_bfloat16*)(smc + O_W02L))[o] = g_w02l[idx];
        ((__nv_bfloat16*)(smc + O_W11H))[o] = g_w11h[idx];
        ((__nv_bfloat16*)(smc + O_W11L))[o] = g_w11l[idx];
        ((__nv_bfloat16*)(smc + O_W12H))[o] = g_w12h[idx];
        ((__nv_bfloat16*)(smc + O_W12L))[o] = g_w12l[idx];
        ((__nv_bfloat16*)(smc + O_W45H))[o] = g_w45h[idx];
        ((__nv_bfloat16*)(smc + O_W45L))[o] = g_w45l[idx];
    }
    for (int idx = tid; idx < 256; idx += NTHR) {
        int n = idx >> 4, k = idx & 15, o = n * P16 + k;
        ((__nv_bfloat16*)(smc + O_W22H))[o] = g_w22h[idx];
        ((__nv_bfloat16*)(smc + O_W22L))[o] = g_w22l[idx];
    }
    for (int idx = tid; idx < 1152; idx += NTHR) {
        int n = idx >> 4, k = idx & 15, o = n * P16 + k;
        ((__nv_bfloat16*)(smc + O_WFH))[o] = g_wfh[idx];
        ((__nv_bfloat16*)(smc + O_WFL))[o] = g_wfl[idx];
    }
    // ---- biases + per-i scalars ----
    if (tid < 32) {
        BS[BI_B02+tid] = b02[tid];
        BS[BI_B11+tid] = b11[tid];
        BS[BI_B12+tid] = b12[tid];
        BS[BI_B45+tid] = (tid < 16) ? b20[tid] : b21[tid-16];
        BS[SC_PREA+tid] = g_preA[i*32+tid];
        BS[SC_PREC+tid] = g_preC[i*32+tid];
    } else if (tid < 48) {
        int t = tid - 32;
        if (t < 16) BS[BI_B22+t] = b22[t];
    } else if (tid < 54) {
        int t = tid - 48;
        BS[SC_PCNI+t] = (t < 3) ? pc[i*3+t] : nrm[i*3+(t-3)];
    }
    for (int idx = tid; idx < 72; idx += NTHR) BS[BI_BF+idx] = (idx < 66) ? bf[idx] : 0.f;
    for (int idx = tid; idx < 128; idx += NTHR) {
        int r = idx >> 5, c = idx & 31;
        BS[SC_W0P+idx] = w0[(80+r)*32 + c];
        BS[SC_W1P+idx] = w1[(80+r)*32 + c];
    }
    __syncthreads();

    const float pix = BS[SC_PCNI+0], piy = BS[SC_PCNI+1], piz = BS[SC_PCNI+2];
    const float nix = BS[SC_PCNI+3], niy = BS[SC_PCNI+4], niz = BS[SC_PCNI+5];

    for (int jt = 0; jt < 4; jt++) {
        const int j = bx*512 + jt*128 + tid;
        // ---- scalar front: ppf + layer-0 linear parts (per-thread pair) ----
        float pv[4];
        {
            float pjx = pc[j*3+0], pjy = pc[j*3+1], pjz = pc[j*3+2];
            float njx = nrm[j*3+0], njy = nrm[j*3+1], njz = nrm[j*3+2];
            float d = dist[(size_t)i*NPTS + j];
            float inv = 1.f / (d + EPSV);
            float x0 = (pix-pjx)*inv, x1v = (piy-pjy)*inv, x2v = (piz-pjz)*inv;
            pv[0] = nix*x0 + niy*x1v + niz*x2v;
            pv[1] = njx*x0 + njy*x1v + njz*x2v;
            pv[2] = nix*njx + niy*njy + niz*njz;
            pv[3] = d;
        }
        float xr[32], h[32];
        {
            const float4* pB = (const float4*)(g_preB + (size_t)j*32);
            const float4* pD = (const float4*)(g_preD + (size_t)j*32);
            const float4* pA = (const float4*)(BS + SC_PREA);
            const float4* pC = (const float4*)(BS + SC_PREC);
#pragma unroll
            for (int q = 0; q < 8; q++) {
                float4 vb = __ldg(pB+q), vd = __ldg(pD+q), va = pA[q], vc = pC[q];
                xr[4*q+0]=va.x+vb.x; xr[4*q+1]=va.y+vb.y; xr[4*q+2]=va.z+vb.z; xr[4*q+3]=va.w+vb.w;
                h[4*q+0]=vc.x+vd.x;  h[4*q+1]=vc.y+vd.y;  h[4*q+2]=vc.z+vd.z;  h[4*q+3]=vc.w+vd.w;
            }
#pragma unroll
            for (int r = 0; r < 4; r++) {
                float p = pv[r];
                const float4* a4 = (const float4*)(BS + SC_W0P + r*32);
                const float4* b4 = (const float4*)(BS + SC_W1P + r*32);
#pragma unroll
                for (int q = 0; q < 8; q++) {
                    float4 a = a4[q], b = b4[q];
                    xr[4*q+0]+=p*a.x; xr[4*q+1]+=p*a.y; xr[4*q+2]+=p*a.z; xr[4*q+3]+=p*a.w;
                    h[4*q+0]+=p*b.x;  h[4*q+1]+=p*b.y;  h[4*q+2]+=p*b.z;  h[4*q+3]+=p*b.w;
                }
            }
#pragma unroll
            for (int c = 0; c < 32; c++) h[c] = fmaxf(h[c], 0.f);
        }
        // stage relu(h) hi/lo (bf16x2) and xr (f32) — warp-local rows
        {
            uint32_t* HH = (uint32_t*)(smc + O_HHI) + tid*17;
            uint32_t* HL = (uint32_t*)(smc + O_HLO) + tid*17;
            float* XP = (float*)(smc + O_XR) + tid*33;
#pragma unroll
            for (int q = 0; q < 16; q++) {
                uint32_t hh = cvt2bf(h[2*q+1], h[2*q]);
                HH[q] = hh;
                HL[q] = lo_resid(hh, h[2*q], h[2*q+1]);
            }
#pragma unroll
            for (int c = 0; c < 32; c++) XP[c] = xr[c];
        }
        __syncwarp();

        const int q0 = lane & 3;
        for (int mt = 0; mt < 2; mt++) {
            const int rbase = w*32 + mt*16;
            const int r0 = rbase + (lane >> 2), r1 = r0 + 8;
            uint32_t ah[2][4], al[2][4];
            {
                const uint32_t* HHb = (const uint32_t*)(smc + O_HHI);
                const uint32_t* HLb = (const uint32_t*)(smc + O_HLO);
#pragma unroll
                for (int kb = 0; kb < 2; kb++) {
                    ah[kb][0] = HHb[r0*17 + kb*8 + q0];
                    ah[kb][1] = HHb[r1*17 + kb*8 + q0];
                    ah[kb][2] = HHb[r0*17 + kb*8 + 4 + q0];
                    ah[kb][3] = HHb[r1*17 + kb*8 + 4 + q0];
                    al[kb][0] = HLb[r0*17 + kb*8 + q0];
                    al[kb][1] = HLb[r1*17 + kb*8 + q0];
                    al[kb][2] = HLb[r0*17 + kb*8 + 4 + q0];
                    al[kb][3] = HLb[r1*17 + kb*8 + 4 + q0];
                }
            }
            float c[4][4], x1[4][4];
            // L1: x1 = relu(h)@W02 + b02 + xr
            gemm_mma<4,2,P32>(c, ah, al, smc+O_W02H, smc+O_W02L, lane);
            {
                const float* XRb = (const float*)(smc + O_XR);
#pragma unroll
                for (int nt = 0; nt < 4; nt++) {
                    int col = nt*8 + q0*2;
                    float bA = BS[BI_B02+col], bB = BS[BI_B02+col+1];
                    x1[nt][0] = c[nt][0] + bA + XRb[r0*33+col];
                    x1[nt][1] = c[nt][1] + bB + XRb[r0*33+col+1];
                    x1[nt][2] = c[nt][2] + bA + XRb[r1*33+col];
                    x1[nt][3] = c[nt][3] + bB + XRb[r1*33+col+1];
                }
            }
            cvt_frag(ah[0], al[0], x1[0], x1[1]);
            cvt_frag(ah[1], al[1], x1[2], x1[3]);
            // L2: h2 = relu(x1@W11 + b11)
            gemm_mma<4,2,P32>(c, ah, al, smc+O_W11H, smc+O_W11L, lane);
#pragma unroll
            for (int nt = 0; nt < 4; nt++) {
                int col = nt*8 + q0*2;
                float bA = BS[BI_B11+col], bB = BS[BI_B11+col+1];
                c[nt][0] = fmaxf(c[nt][0]+bA, 0.f);
                c[nt][1] = fmaxf(c[nt][1]+bB, 0.f);
                c[nt][2] = fmaxf(c[nt][2]+bA, 0.f);
                c[nt][3] = fmaxf(c[nt][3]+bB, 0.f);
            }
            cvt_frag(ah[0], al[0], c[0], c[1]);
            cvt_frag(ah[1], al[1], c[2], c[3]);
            // L3: x2 = h2@W12 + b12 + x1  (into x1)
            gemm_mma<4,2,P32>(c, ah, al, smc+O_W12H, smc+O_W12L, lane);
#pragma unroll
            for (int nt = 0; nt < 4; nt++) {
                int col = nt*8 + q0*2;
                float bA = BS[BI_B12+col], bB = BS[BI_B12+col+1];
                x1[nt][0] += c[nt][0] + bA;
                x1[nt][1] += c[nt][1] + bB;
                x1[nt][2] += c[nt][2] + bA;
                x1[nt][3] += c[nt][3] + bB;
            }
            cvt_frag(ah[0], al[0], x1[0], x1[1]);
            cvt_frag(ah[1], al[1], x1[2], x1[3]);
            // L4: [R|H] = x2 @ [W20|W21]
            gemm_mma<4,2,P32>(c, ah, al, smc+O_W45H, smc+O_W45L, lane);
            float R[2][4];
#pragma unroll
            for (int t = 0; t < 2; t++) {
                int col = t*8 + q0*2;
                float bA = BS[BI_B45+col], bB = BS[BI_B45+col+1];
                R[t][0] = c[t][0]+bA; R[t][1] = c[t][1]+bB;
                R[t][2] = c[t][2]+bA; R[t][3] = c[t][3]+bB;
                float hA = BS[BI_B45+16+col], hB = BS[BI_B45+16+col+1];
                c[2+t][0] = fmaxf(c[2+t][0]+hA, 0.f);
                c[2+t][1] = fmaxf(c[2+t][1]+hB, 0.f);
                c[2+t][2] = fmaxf(c[2+t][2]+hA, 0.f);
                c[2+t][3] = fmaxf(c[2+t][3]+hB, 0.f);
            }
            // L5: x3 = relu(H)@W22 + b22 + R  (into R)
            cvt_frag(ah[0], al[0], c[2], c[3]);
            float c2[2][4];
            gemm_mma<2,1,P16>(c2, ah, al, smc+O_W22H, smc+O_W22L, lane);
#pragma unroll
            for (int t = 0; t < 2; t++) {
                int col = t*8 + q0*2;
                float bA = BS[BI_B22+col], bB = BS[BI_B22+col+1];
                R[t][0] += c2[t][0]+bA; R[t][1] += c2[t][1]+bB;
                R[t][2] += c2[t][2]+bA; R[t][3] += c2[t][3]+bB;
            }
            // L6: out = x3 @ WF (+bf), N=72 (cols>=66 are zero-weight pads)
            cvt_frag(ah[0], al[0], R[0], R[1]);
            float cf[9][4];
            gemm_mma<9,1,P16>(cf, ah, al, smc+O_WFH, smc+O_WFL, lane);
            // scatter to warp-private staging, then coalesced flush (1056 f32 contiguous)
            float* so = (float*)(smc + O_OUT) + w*(16*67);
            const int sr0 = lane >> 2, sr1 = sr0 + 8;
#pragma unroll
            for (int nt = 0; nt < 9; nt++) {
                int col = nt*8 + q0*2;
                if (col < 66) {
                    float b = BS[BI_BF+col];
                    so[sr0*67+col] = cf[nt][0]+b;
                    so[sr1*67+col] = cf[nt][2]+b;
                }
                if (col+1 < 66) {
                    float b = BS[BI_BF+col+1];
                    so[sr0*67+col+1] = cf[nt][1]+b;
                    so[sr1*67+col+1] = cf[nt][3]+b;
                }
            }
            __syncwarp();
            size_t gbase = ((size_t)i*NPTS + (size_t)bx*512 + jt*128 + rbase) * 66;
#pragma unroll 4
            for (int s = 0; s < 33; s++) {
                int idx = s*32 + lane;
                int jj = idx / 66, cc = idx - jj*66;
                out[gbase + idx] = so[jj*67 + cc];
            }
            __syncwarp();
        }
    }
}

extern "C" void kernel_launch(void* const* d_in, const int* in_sizes, int n_in,
                              void* d_out, int out_size) {
    const float* pc   = (const float*)d_in[0];
    const float* nrm  = (const float*)d_in[1];
    const float* dist = (const float*)d_in[2];
    const float* feat = (const float*)d_in[3];
    const float* w0   = (const float*)d_in[4];
    const float* b0   = (const float*)d_in[5];
    const float* w1   = (const float*)d_in[6];
    const float* b1   = (const float*)d_in[7];
    const float* w02  = (const float*)d_in[8];
    const float* b02  = (const float*)d_in[9];
    const float* w11  = (const float*)d_in[10];
    const float* b11  = (const float*)d_in[11];
    const float* w12  = (const float*)d_in[12];
    const float* b12  = (const float*)d_in[13];
    const float* w20  = (const float*)d_in[14];
    const float* b20  = (const float*)d_in[15];
    const float* w21  = (const float*)d_in[16];
    const float* b21  = (const float*)d_in[17];
    const float* w22  = (const float*)d_in[18];
    const float* b22  = (const float*)d_in[19];
    const float* wf   = (const float*)d_in[20];
    const float* bf   = (const float*)d_in[21];
    float* out = (float*)d_out;

    cudaFuncSetAttribute(ppf_mma_kernel, cudaFuncAttributeMaxDynamicSharedMemorySize, SMEM_BYTES);

    prep_pre<<<NPTS, 32>>>(feat, w0, b0, w1, b1);
    prep_split<<<1, 256>>>(w02, w11, w12, w20, w21, w22, wf);

    dim3 grid(2, NPTS);
    ppf_mma_kernel<<<grid, NTHR, SMEM_BYTES>>>(
        pc, nrm, dist, w0, w1,
        b02, b11, b12, b20, b21, b22, bf, out);
}

// round 14
// speedup vs baseline: 1.9097x; 1.0710x over previous
#include <cuda_runtime.h>
#include <cuda_bf16.h>
#include <stdint.h>

#define NPTS 1024
#define FDIM 40
#define EPSV 1e-7f
#define NTHR 128

// ---------------- device globals ----------------
__device__ float g_preA[NPTS*32], g_preB[NPTS*32], g_preC[NPTS*32], g_preD[NPTS*32];
__device__ __nv_bfloat16 g_w02h[1024], g_w02l[1024], g_w11h[1024], g_w11l[1024];
__device__ __nv_bfloat16 g_w12h[1024], g_w12l[1024], g_w45h[1024], g_w45l[1024];
__device__ __nv_bfloat16 g_w22h[256],  g_w22l[256],  g_wfh[1152],  g_wfl[1152];

__device__ __forceinline__ void bsplit(float v, __nv_bfloat16* H, __nv_bfloat16* L, int i) {
    __nv_bfloat16 h = __float2bfloat16(v);
    H[i] = h; L[i] = __float2bfloat16(v - __bfloat162float(h));
}

// merged prep: blocks 0..255 compute pre (4 points each), blocks 256..271 do weight splits
__global__ void prep_all(const float* __restrict__ feat,
                         const float* __restrict__ w0, const float* __restrict__ b0,
                         const float* __restrict__ w1, const float* __restrict__ b1,
                         const float* __restrict__ w02, const float* __restrict__ w11,
                         const float* __restrict__ w12, const float* __restrict__ w20,
                         const float* __restrict__ w21, const float* __restrict__ w22,
                         const float* __restrict__ wf) {
    int b = blockIdx.x, t = threadIdx.x;
    if (b < 256) {
        int p = b*4 + (t >> 5), c = t & 31;
        float a = b0[c], bb = 0.f, cc = b1[c], dd = 0.f;
#pragma unroll 8
        for (int k = 0; k < FDIM; k++) {
            float f = feat[p*FDIM+k];
            a  += f*w0[k*32+c];  bb += f*w0[(FDIM+k)*32+c];
            cc += f*w1[k*32+c];  dd += f*w1[(FDIM+k)*32+c];
        }
        g_preA[p*32+c]=a; g_preB[p*32+c]=bb; g_preC[p*32+c]=cc; g_preD[p*32+c]=dd;
    } else {
        for (int idx = (b-256)*128 + t; idx < 5504; idx += 16*128) {
            if (idx < 1024) {
                int i = idx, n = i >> 5, k = i & 31;
                bsplit(w02[k*32+n], g_w02h, g_w02l, i);
            } else if (idx < 2048) {
                int i = idx - 1024, n = i >> 5, k = i & 31;
                bsplit(w11[k*32+n], g_w11h, g_w11l, i);
            } else if (idx < 3072) {
                int i = idx - 2048, n = i >> 5, k = i & 31;
                bsplit(w12[k*32+n], g_w12h, g_w12l, i);
            } else if (idx < 4096) {
                int i = idx - 3072, n = i >> 5, k = i & 31;
                float v45 = (n < 16) ? w20[k*16+n] : w21[k*16+(n-16)];
                bsplit(v45, g_w45h, g_w45l, i);
            } else if (idx < 4352) {
                int i = idx - 4096, n = i >> 4, k = i & 15;
                bsplit(w22[k*16+n], g_w22h, g_w22l, i);
            } else {
                int i = idx - 4352, n = i >> 4, k = i & 15;
                bsplit(n < 66 ? wf[k*66+n] : 0.f, g_wfh, g_wfl, i);
            }
        }
    }
}

// ---------------- mma helpers ----------------
__device__ __forceinline__ uint32_t cvt2bf(float hi, float lo) {
    uint32_t r; asm("cvt.rn.bf16x2.f32 %0, %1, %2;" : "=r"(r) : "f"(hi), "f"(lo)); return r;
}
__device__ __forceinline__ uint32_t lo_resid(uint32_t h, float f0, float f1) {
    float h0 = __uint_as_float(h << 16);
    float h1 = __uint_as_float(h & 0xffff0000u);
    return cvt2bf(f1 - h1, f0 - h0);
}
__device__ __forceinline__ void mma16816(float* c, const uint32_t* a, const uint32_t* b) {
    asm volatile("mma.sync.aligned.m16n8k16.row.col.f32.bf16.bf16.f32 "
        "{%0,%1,%2,%3}, {%4,%5,%6,%7}, {%8,%9}, {%0,%1,%2,%3};"
        : "+f"(c[0]), "+f"(c[1]), "+f"(c[2]), "+f"(c[3])
        : "r"(a[0]), "r"(a[1]), "r"(a[2]), "r"(a[3]), "r"(b[0]), "r"(b[1]));
}
template<int NT, int KS, int P>
__device__ __forceinline__ void gemm_mma(float c[][4],
        const uint32_t ah[][4], const uint32_t al[][4],
        const char* wh, const char* wl, int lane) {
#pragma unroll
    for (int nt = 0; nt < NT; nt++) { c[nt][0]=0.f; c[nt][1]=0.f; c[nt][2]=0.f; c[nt][3]=0.f; }
    const int n0 = lane >> 2, k0 = (lane & 3) * 2;
#pragma unroll
    for (int ks = 0; ks < KS; ks++) {
#pragma unroll
        for (int nt = 0; nt < NT; nt++) {
            const char* ph = wh + ((nt*8 + n0) * P + ks*16 + k0) * 2;
            uint32_t bh[2] = { *(const uint32_t*)ph, *(const uint32_t*)(ph + 16) };
            mma16816(c[nt], ah[ks], bh);
            mma16816(c[nt], al[ks], bh);
            const char* pl = wl + ((nt*8 + n0) * P + ks*16 + k0) * 2;
            uint32_t bl[2] = { *(const uint32_t*)pl, *(const uint32_t*)(pl + 16) };
            mma16816(c[nt], ah[ks], bl);
        }
    }
}
__device__ __forceinline__ void cvt_frag(uint32_t* ah, uint32_t* al, const float* cA, const float* cB) {
    ah[0] = cvt2bf(cA[1], cA[0]); al[0] = lo_resid(ah[0], cA[0], cA[1]);
    ah[1] = cvt2bf(cA[3], cA[2]); al[1] = lo_resid(ah[1], cA[2], cA[3]);
    ah[2] = cvt2bf(cB[1], cB[0]); al[2] = lo_resid(ah[2], cB[0], cB[1]);
    ah[3] = cvt2bf(cB[3], cB[2]); al[3] = lo_resid(ah[3], cB[2], cB[3]);
}

// ---------------- smem layout (bytes) ----------------
#define P32 40
#define P16 24
#define O_W02H 0
#define O_W02L 2560
#define O_W11H 5120
#define O_W11L 7680
#define O_W12H 10240
#define O_W12L 12800
#define O_W45H 15360
#define O_W45L 17920
#define O_W22H 20480
#define O_W22L 21248
#define O_WFH  22016
#define O_WFL  25472
#define O_SC   28928   /* f32[544] */
#define BI_B02 0
#define BI_B11 32
#define BI_B12 64
#define BI_B45 96
#define BI_B22 128
#define BI_BF  144
#define SC_W0P 216
#define SC_W1P 344
#define SC_PREA 472
#define SC_PREC 504
#define SC_PCNI 536
#define O_HHI  31104   /* u32[128*17] */
#define O_HLO  39808
#define O_XR   48512   /* f32[128*33] */
#define O_OUT  65408   /* f32[4 warps][32*67] */
#define SMEM_BYTES (O_OUT + 4*32*67*4)

__global__ __launch_bounds__(NTHR) void ppf_mma_kernel(
    const float* __restrict__ pc, const float* __restrict__ nrm,
    const float* __restrict__ dist,
    const float* __restrict__ w0,  const float* __restrict__ w1,
    const float* __restrict__ b02, const float* __restrict__ b11, const float* __restrict__ b12,
    const float* __restrict__ b20, const float* __restrict__ b21, const float* __restrict__ b22,
    const float* __restrict__ bf,  float* __restrict__ out)
{
    extern __shared__ char smc[];
    float* BS = (float*)(smc + O_SC);
    const int tid = threadIdx.x, lane = tid & 31, w = tid >> 5;
    const int i = blockIdx.y, bx = blockIdx.x;

    // ---- stage weights (dense [N][K] -> pitched) ----
    for (int idx = tid; idx < 1024; idx += NTHR) {
        int n = idx >> 5, k = idx & 31, o = n * P32 + k;
        ((__nv_bfloat16*)(smc + O_W02H))[o] = g_w02h[idx];
        ((__nv_bfloat16*)(smc + O_W02L))[o] = g_w02l[idx];
        ((__nv_bfloat16*)(smc + O_W11H))[o] = g_w11h[idx];
        ((__nv_bfloat16*)(smc + O_W11L))[o] = g_w11l[idx];
        ((__nv_bfloat16*)(smc + O_W12H))[o] = g_w12h[idx];
        ((__nv_bfloat16*)(smc + O_W12L))[o] = g_w12l[idx];
        ((__nv_bfloat16*)(smc + O_W45H))[o] = g_w45h[idx];
        ((__nv_bfloat16*)(smc + O_W45L))[o] = g_w45l[idx];
    }
    for (int idx = tid; idx < 256; idx += NTHR) {
        int n = idx >> 4, k = idx & 15, o = n * P16 + k;
        ((__nv_bfloat16*)(smc + O_W22H))[o] = g_w22h[idx];
        ((__nv_bfloat16*)(smc + O_W22L))[o] = g_w22l[idx];
    }
    for (int idx = tid; idx < 1152; idx += NTHR) {
        int n = idx >> 4, k = idx & 15, o = n * P16 + k;
        ((__nv_bfloat16*)(smc + O_WFH))[o] = g_wfh[idx];
        ((__nv_bfloat16*)(smc + O_WFL))[o] = g_wfl[idx];
    }
    if (tid < 32) {
        BS[BI_B02+tid] = b02[tid];
        BS[BI_B11+tid] = b11[tid];
        BS[BI_B12+tid] = b12[tid];
        BS[BI_B45+tid] = (tid < 16) ? b20[tid] : b21[tid-16];
        BS[SC_PREA+tid] = g_preA[i*32+tid];
        BS[SC_PREC+tid] = g_preC[i*32+tid];
    } else if (tid < 48) {
        int t = tid - 32;
        if (t < 16) BS[BI_B22+t] = b22[t];
    } else if (tid < 54) {
        int t = tid - 48;
        BS[SC_PCNI+t] = (t < 3) ? pc[i*3+t] : nrm[i*3+(t-3)];
    }
    for (int idx = tid; idx < 72; idx += NTHR) BS[BI_BF+idx] = (idx < 66) ? bf[idx] : 0.f;
    for (int idx = tid; idx < 128; idx += NTHR) {
        int r = idx >> 5, c = idx & 31;
        BS[SC_W0P+idx] = w0[(80+r)*32 + c];
        BS[SC_W1P+idx] = w1[(80+r)*32 + c];
    }
    __syncthreads();

    const float pix = BS[SC_PCNI+0], piy = BS[SC_PCNI+1], piz = BS[SC_PCNI+2];
    const float nix = BS[SC_PCNI+3], niy = BS[SC_PCNI+4], niz = BS[SC_PCNI+5];

    for (int jt = 0; jt < 4; jt++) {
        const int j = bx*512 + jt*128 + tid;
        // ---- scalar front: ppf + layer-0 linear parts ----
        float pv[4];
        {
            float pjx = pc[j*3+0], pjy = pc[j*3+1], pjz = pc[j*3+2];
            float njx = nrm[j*3+0], njy = nrm[j*3+1], njz = nrm[j*3+2];
            float d = dist[(size_t)i*NPTS + j];
            float inv = 1.f / (d + EPSV);
            float x0 = (pix-pjx)*inv, x1v = (piy-pjy)*inv, x2v = (piz-pjz)*inv;
            pv[0] = nix*x0 + niy*x1v + niz*x2v;
            pv[1] = njx*x0 + njy*x1v + njz*x2v;
            pv[2] = nix*njx + niy*njy + niz*njz;
            pv[3] = d;
        }
        float xr[32], h[32];
        {
            const float4* pB = (const float4*)(g_preB + (size_t)j*32);
            const float4* pD = (const float4*)(g_preD + (size_t)j*32);
            const float4* pA = (const float4*)(BS + SC_PREA);
            const float4* pC = (const float4*)(BS + SC_PREC);
#pragma unroll
            for (int q = 0; q < 8; q++) {
                float4 vb = __ldg(pB+q), vd = __ldg(pD+q), va = pA[q], vc = pC[q];
                xr[4*q+0]=va.x+vb.x; xr[4*q+1]=va.y+vb.y; xr[4*q+2]=va.z+vb.z; xr[4*q+3]=va.w+vb.w;
                h[4*q+0]=vc.x+vd.x;  h[4*q+1]=vc.y+vd.y;  h[4*q+2]=vc.z+vd.z;  h[4*q+3]=vc.w+vd.w;
            }
#pragma unroll
            for (int r = 0; r < 4; r++) {
                float p = pv[r];
                const float4* a4 = (const float4*)(BS + SC_W0P + r*32);
                const float4* b4 = (const float4*)(BS + SC_W1P + r*32);
#pragma unroll
                for (int q = 0; q < 8; q++) {
                    float4 a = a4[q], b = b4[q];
                    xr[4*q+0]+=p*a.x; xr[4*q+1]+=p*a.y; xr[4*q+2]+=p*a.z; xr[4*q+3]+=p*a.w;
                    h[4*q+0]+=p*b.x;  h[4*q+1]+=p*b.y;  h[4*q+2]+=p*b.z;  h[4*q+3]+=p*b.w;
                }
            }
#pragma unroll
            for (int c = 0; c < 32; c++) h[c] = fmaxf(h[c], 0.f);
        }
        // stage relu(h) hi/lo and xr — warp-local rows
        {
            uint32_t* HH = (uint32_t*)(smc + O_HHI) + tid*17;
            uint32_t* HL = (uint32_t*)(smc + O_HLO) + tid*17;
            float* XP = (float*)(smc + O_XR) + tid*33;
#pragma unroll
            for (int q = 0; q < 16; q++) {
                uint32_t hh = cvt2bf(h[2*q+1], h[2*q]);
                HH[q] = hh;
                HL[q] = lo_resid(hh, h[2*q], h[2*q+1]);
            }
#pragma unroll
            for (int c = 0; c < 32; c++) XP[c] = xr[c];
        }
        __syncwarp();

        const int q0 = lane & 3;
        // ---- both 16-row tiles interleaved (2x independent HMMA chains) ----
        uint32_t ah[2][2][4], al[2][2][4];
        int r0[2], r1[2];
        {
            const uint32_t* HHb = (const uint32_t*)(smc + O_HHI);
            const uint32_t* HLb = (const uint32_t*)(smc + O_HLO);
#pragma unroll
            for (int hh = 0; hh < 2; hh++) {
                r0[hh] = w*32 + hh*16 + (lane >> 2);
                r1[hh] = r0[hh] + 8;
#pragma unroll
                for (int kb = 0; kb < 2; kb++) {
                    ah[hh][kb][0] = HHb[r0[hh]*17 + kb*8 + q0];
                    ah[hh][kb][1] = HHb[r1[hh]*17 + kb*8 + q0];
                    ah[hh][kb][2] = HHb[r0[hh]*17 + kb*8 + 4 + q0];
                    ah[hh][kb][3] = HHb[r1[hh]*17 + kb*8 + 4 + q0];
                    al[hh][kb][0] = HLb[r0[hh]*17 + kb*8 + q0];
                    al[hh][kb][1] = HLb[r1[hh]*17 + kb*8 + q0];
                    al[hh][kb][2] = HLb[r0[hh]*17 + kb*8 + 4 + q0];
                    al[hh][kb][3] = HLb[r1[hh]*17 + kb*8 + 4 + q0];
                }
            }
        }
        float c[2][4][4], x1[2][4][4];
        // L1: x1 = relu(h)@W02 + b02 + xr
#pragma unroll
        for (int hh = 0; hh < 2; hh++)
            gemm_mma<4,2,P32>(c[hh], ah[hh], al[hh], smc+O_W02H, smc+O_W02L, lane);
        {
            const float* XRb = (const float*)(smc + O_XR);
#pragma unroll
            for (int hh = 0; hh < 2; hh++)
#pragma unroll
            for (int nt = 0; nt < 4; nt++) {
                int col = nt*8 + q0*2;
                float bA = BS[BI_B02+col], bB = BS[BI_B02+col+1];
                x1[hh][nt][0] = c[hh][nt][0] + bA + XRb[r0[hh]*33+col];
                x1[hh][nt][1] = c[hh][nt][1] + bB + XRb[r0[hh]*33+col+1];
                x1[hh][nt][2] = c[hh][nt][2] + bA + XRb[r1[hh]*33+col];
                x1[hh][nt][3] = c[hh][nt][3] + bB + XRb[r1[hh]*33+col+1];
            }
        }
#pragma unroll
        for (int hh = 0; hh < 2; hh++) {
            cvt_frag(ah[hh][0], al[hh][0], x1[hh][0], x1[hh][1]);
            cvt_frag(ah[hh][1], al[hh][1], x1[hh][2], x1[hh][3]);
        }
        // L2: h2 = relu(x1@W11 + b11)
#pragma unroll
        for (int hh = 0; hh < 2; hh++)
            gemm_mma<4,2,P32>(c[hh], ah[hh], al[hh], smc+O_W11H, smc+O_W11L, lane);
#pragma unroll
        for (int hh = 0; hh < 2; hh++)
#pragma unroll
        for (int nt = 0; nt < 4; nt++) {
            int col = nt*8 + q0*2;
            float bA = BS[BI_B11+col], bB = BS[BI_B11+col+1];
            c[hh][nt][0] = fmaxf(c[hh][nt][0]+bA, 0.f);
            c[hh][nt][1] = fmaxf(c[hh][nt][1]+bB, 0.f);
            c[hh][nt][2] = fmaxf(c[hh][nt][2]+bA, 0.f);
            c[hh][nt][3] = fmaxf(c[hh][nt][3]+bB, 0.f);
        }
#pragma unroll
        for (int hh = 0; hh < 2; hh++) {
            cvt_frag(ah[hh][0], al[hh][0], c[hh][0], c[hh][1]);
            cvt_frag(ah[hh][1], al[hh][1], c[hh][2], c[hh][3]);
        }
        // L3: x2 = h2@W12 + b12 + x1  (into x1)
#pragma unroll
        for (int hh = 0; hh < 2; hh++)
            gemm_mma<4,2,P32>(c[hh], ah[hh], al[hh], smc+O_W12H, smc+O_W12L, lane);
#pragma unroll
        for (int hh = 0; hh < 2; hh++)
#pragma unroll
        for (int nt = 0; nt < 4; nt++) {
            int col = nt*8 + q0*2;
            float bA = BS[BI_B12+col], bB = BS[BI_B12+col+1];
            x1[hh][nt][0] += c[hh][nt][0] + bA;
            x1[hh][nt][1] += c[hh][nt][1] + bB;
            x1[hh][nt][2] += c[hh][nt][2] + bA;
            x1[hh][nt][3] += c[hh][nt][3] + bB;
        }
#pragma unroll
        for (int hh = 0; hh < 2; hh++) {
            cvt_frag(ah[hh][0], al[hh][0], x1[hh][0], x1[hh][1]);
            cvt_frag(ah[hh][1], al[hh][1], x1[hh][2], x1[hh][3]);
        }
        // L4: [R|H] = x2 @ [W20|W21]
#pragma unroll
        for (int hh = 0; hh < 2; hh++)
            gemm_mma<4,2,P32>(c[hh], ah[hh], al[hh], smc+O_W45H, smc+O_W45L, lane);
        float R[2][2][4];
#pragma unroll
        for (int hh = 0; hh < 2; hh++)
#pragma unroll
        for (int t = 0; t < 2; t++) {
            int col = t*8 + q0*2;
            float bA = BS[BI_B45+col], bB = BS[BI_B45+col+1];
            R[hh][t][0] = c[hh][t][0]+bA; R[hh][t][1] = c[hh][t][1]+bB;
            R[hh][t][2] = c[hh][t][2]+bA; R[hh][t][3] = c[hh][t][3]+bB;
            float hA = BS[BI_B45+16+col], hB = BS[BI_B45+16+col+1];
            c[hh][2+t][0] = fmaxf(c[hh][2+t][0]+hA, 0.f);
            c[hh][2+t][1] = fmaxf(c[hh][2+t][1]+hB, 0.f);
            c[hh][2+t][2] = fmaxf(c[hh][2+t][2]+hA, 0.f);
            c[hh][2+t][3] = fmaxf(c[hh][2+t][3]+hB, 0.f);
        }
        // L5: x3 = relu(H)@W22 + b22 + R
#pragma unroll
        for (int hh = 0; hh < 2; hh++)
            cvt_frag(ah[hh][0], al[hh][0], c[hh][2], c[hh][3]);
        float c2[2][2][4];
#pragma unroll
        for (int hh = 0; hh < 2; hh++)
            gemm_mma<2,1,P16>(c2[hh], ah[hh], al[hh], smc+O_W22H, smc+O_W22L, lane);
#pragma unroll
        for (int hh = 0; hh < 2; hh++)
#pragma unroll
        for (int t = 0; t < 2; t++) {
            int col = t*8 + q0*2;
            float bA = BS[BI_B22+col], bB = BS[BI_B22+col+1];
            R[hh][t][0] += c2[hh][t][0]+bA; R[hh][t][1] += c2[hh][t][1]+bB;
            R[hh][t][2] += c2[hh][t][2]+bA; R[hh][t][3] += c2[hh][t][3]+bB;
        }
        // L6 per tile (bounds register peak): out = x3 @ WF (+bf)
        float* so = (float*)(smc + O_OUT) + w*(32*67);
        const int sr = lane >> 2;
#pragma unroll
        for (int hh = 0; hh < 2; hh++) {
            cvt_frag(ah[hh][0], al[hh][0], R[hh][0], R[hh][1]);
            float cf[9][4];
            gemm_mma<9,1,P16>(cf, ah[hh], al[hh], smc+O_WFH, smc+O_WFL, lane);
            int s0 = hh*16 + sr, s1 = s0 + 8;
#pragma unroll
            for (int nt = 0; nt < 9; nt++) {
                int col = nt*8 + q0*2;
                if (col < 66) {
                    float b = BS[BI_BF+col];
                    so[s0*67+col] = cf[nt][0]+b;
                    so[s1*67+col] = cf[nt][2]+b;
                }
                if (col+1 < 66) {
                    float b = BS[BI_BF+col+1];
                    so[s0*67+col+1] = cf[nt][1]+b;
                    so[s1*67+col+1] = cf[nt][3]+b;
                }
            }
        }
        __syncwarp();
        // coalesced flush: 32 rows * 66 = 2112 contiguous floats per warp
        size_t gbase = ((size_t)i*NPTS + (size_t)bx*512 + jt*128 + w*32) * 66;
#pragma unroll 6
        for (int s = 0; s < 66; s++) {
            int idx = s*32 + lane;
            int jj = idx / 66, cc = idx - jj*66;
            out[gbase + idx] = so[jj*67 + cc];
        }
        __syncwarp();
    }
}

extern "C" void kernel_launch(void* const* d_in, const int* in_sizes, int n_in,
                              void* d_out, int out_size) {
    const float* pc   = (const float*)d_in[0];
    const float* nrm  = (const float*)d_in[1];
    const float* dist = (const float*)d_in[2];
    const float* feat = (const float*)d_in[3];
    const float* w0   = (const float*)d_in[4];
    const float* b0   = (const float*)d_in[5];
    const float* w1   = (const float*)d_in[6];
    const float* b1   = (const float*)d_in[7];
    const float* w02  = (const float*)d_in[8];
    const float* b02  = (const float*)d_in[9];
    const float* w11  = (const float*)d_in[10];
    const float* b11  = (const float*)d_in[11];
    const float* w12  = (const float*)d_in[12];
    const float* b12  = (const float*)d_in[13];
    const float* w20  = (const float*)d_in[14];
    const float* b20  = (const float*)d_in[15];
    const float* w21  = (const float*)d_in[16];
    const float* b21  = (const float*)d_in[17];
    const float* w22  = (const float*)d_in[18];
    const float* b22  = (const float*)d_in[19];
    const float* wf   = (const float*)d_in[20];
    const float* bf   = (const float*)d_in[21];
    float* out = (float*)d_out;

    cudaFuncSetAttribute(ppf_mma_kernel, cudaFuncAttributeMaxDynamicSharedMemorySize, SMEM_BYTES);

    prep_all<<<272, NTHR>>>(feat, w0, b0, w1, b1, w02, w11, w12, w20, w21, w22, wf);

    dim3 grid(2, NPTS);
    ppf_mma_kernel<<<grid, NTHR, SMEM_BYTES>>>(
        pc, nrm, dist, w0, w1,
        b02, b11, b12, b20, b21, b22, bf, out);
}

// round 17
// speedup vs baseline: 1.9367x; 1.0142x over previous
#include <cuda_runtime.h>
#include <cuda_bf16.h>
#include <stdint.h>

#define NPTS 1024
#define FDIM 40
#define EPSV 1e-7f
#define NTHR 128

// ---------------- device globals ----------------
__device__ float g_preA[NPTS*32], g_preB[NPTS*32], g_preC[NPTS*32], g_preD[NPTS*32];
__device__ __nv_bfloat16 g_w02h[1024], g_w02l[1024], g_w11h[1024], g_w11l[1024];
__device__ __nv_bfloat16 g_w12h[1024], g_w12l[1024], g_w45h[1024], g_w45l[1024];
__device__ __nv_bfloat16 g_w22h[256],  g_w22l[256],  g_wfh[1152],  g_wfl[1152];

__device__ __forceinline__ void bsplit(float v, __nv_bfloat16* H, __nv_bfloat16* L, int i) {
    __nv_bfloat16 h = __float2bfloat16(v);
    H[i] = h; L[i] = __float2bfloat16(v - __bfloat162float(h));
}

// merged prep: blocks 0..255 compute pre (4 points each), blocks 256..271 do weight splits
__global__ void prep_all(const float* __restrict__ feat,
                         const float* __restrict__ w0, const float* __restrict__ b0,
                         const float* __restrict__ w1, const float* __restrict__ b1,
                         const float* __restrict__ w02, const float* __restrict__ w11,
                         const float* __restrict__ w12, const float* __restrict__ w20,
                         const float* __restrict__ w21, const float* __restrict__ w22,
                         const float* __restrict__ wf) {
    int b = blockIdx.x, t = threadIdx.x;
    if (b < 256) {
        int p = b*4 + (t >> 5), c = t & 31;
        float a = b0[c], bb = 0.f, cc = b1[c], dd = 0.f;
#pragma unroll 8
        for (int k = 0; k < FDIM; k++) {
            float f = feat[p*FDIM+k];
            a  += f*w0[k*32+c];  bb += f*w0[(FDIM+k)*32+c];
            cc += f*w1[k*32+c];  dd += f*w1[(FDIM+k)*32+c];
        }
        g_preA[p*32+c]=a; g_preB[p*32+c]=bb; g_preC[p*32+c]=cc; g_preD[p*32+c]=dd;
    } else {
        for (int idx = (b-256)*128 + t; idx < 5504; idx += 16*128) {
            if (idx < 1024) {
                int i = idx, n = i >> 5, k = i & 31;
                bsplit(w02[k*32+n], g_w02h, g_w02l, i);
            } else if (idx < 2048) {
                int i = idx - 1024, n = i >> 5, k = i & 31;
                bsplit(w11[k*32+n], g_w11h, g_w11l, i);
            } else if (idx < 3072) {
                int i = idx - 2048, n = i >> 5, k = i & 31;
                bsplit(w12[k*32+n], g_w12h, g_w12l, i);
            } else if (idx < 4096) {
                int i = idx - 3072, n = i >> 5, k = i & 31;
                float v45 = (n < 16) ? w20[k*16+n] : w21[k*16+(n-16)];
                bsplit(v45, g_w45h, g_w45l, i);
            } else if (idx < 4352) {
                int i = idx - 4096, n = i >> 4, k = i & 15;
                bsplit(w22[k*16+n], g_w22h, g_w22l, i);
            } else {
                int i = idx - 4352, n = i >> 4, k = i & 15;
                bsplit(n < 66 ? wf[k*66+n] : 0.f, g_wfh, g_wfl, i);
            }
        }
    }
}

// ---------------- mma helpers ----------------
__device__ __forceinline__ uint32_t cvt2bf(float hi, float lo) {
    uint32_t r; asm("cvt.rn.bf16x2.f32 %0, %1, %2;" : "=r"(r) : "f"(hi), "f"(lo)); return r;
}
__device__ __forceinline__ uint32_t lo_resid(uint32_t h, float f0, float f1) {
    float h0 = __uint_as_float(h << 16);
    float h1 = __uint_as_float(h & 0xffff0000u);
    return cvt2bf(f1 - h1, f0 - h0);
}
__device__ __forceinline__ void mma16816(float* c, const uint32_t* a, const uint32_t* b) {
    asm volatile("mma.sync.aligned.m16n8k16.row.col.f32.bf16.bf16.f32 "
        "{%0,%1,%2,%3}, {%4,%5,%6,%7}, {%8,%9}, {%0,%1,%2,%3};"
        : "+f"(c[0]), "+f"(c[1]), "+f"(c[2]), "+f"(c[3])
        : "r"(a[0]), "r"(a[1]), "r"(a[2]), "r"(a[3]), "r"(b[0]), "r"(b[1]));
}
// DUAL-tile GEMM: both 16-row tiles consume the SAME weight fragments.
// Each bh/bl load feeds 6 MMAs (3 split terms x 2 tiles) -> halves B-operand LDS.
template<int NT, int KS, int P>
__device__ __forceinline__ void gemm_mma_dual(float c0[][4], float c1[][4],
        const uint32_t ah0[][4], const uint32_t al0[][4],
        const uint32_t ah1[][4], const uint32_t al1[][4],
        const char* wh, const char* wl, int lane) {
#pragma unroll
    for (int nt = 0; nt < NT; nt++) {
        c0[nt][0]=0.f; c0[nt][1]=0.f; c0[nt][2]=0.f; c0[nt][3]=0.f;
        c1[nt][0]=0.f; c1[nt][1]=0.f; c1[nt][2]=0.f; c1[nt][3]=0.f;
    }
    const int n0 = lane >> 2, k0 = (lane & 3) * 2;
#pragma unroll
    for (int ks = 0; ks < KS; ks++) {
#pragma unroll
        for (int nt = 0; nt < NT; nt++) {
            const char* ph = wh + ((nt*8 + n0) * P + ks*16 + k0) * 2;
            uint32_t bh[2] = { *(const uint32_t*)ph, *(const uint32_t*)(ph + 16) };
            const char* pl = wl + ((nt*8 + n0) * P + ks*16 + k0) * 2;
            uint32_t bl[2] = { *(const uint32_t*)pl, *(const uint32_t*)(pl + 16) };
            mma16816(c0[nt], ah0[ks], bh);
            mma16816(c1[nt], ah1[ks], bh);
            mma16816(c0[nt], al0[ks], bh);
            mma16816(c1[nt], al1[ks], bh);
            mma16816(c0[nt], ah0[ks], bl);
            mma16816(c1[nt], ah1[ks], bl);
        }
    }
}
__device__ __forceinline__ void cvt_frag(uint32_t* ah, uint32_t* al, const float* cA, const float* cB) {
    ah[0] = cvt2bf(cA[1], cA[0]); al[0] = lo_resid(ah[0], cA[0], cA[1]);
    ah[1] = cvt2bf(cA[3], cA[2]); al[1] = lo_resid(ah[1], cA[2], cA[3]);
    ah[2] = cvt2bf(cB[1], cB[0]); al[2] = lo_resid(ah[2], cB[0], cB[1]);
    ah[3] = cvt2bf(cB[3], cB[2]); al[3] = lo_resid(ah[3], cB[2], cB[3]);
}

// ---------------- smem layout (bytes) ----------------
#define P32 40
#define P16 24
#define O_W02H 0
#define O_W02L 2560
#define O_W11H 5120
#define O_W11L 7680
#define O_W12H 10240
#define O_W12L 12800
#define O_W45H 15360
#define O_W45L 17920
#define O_W22H 20480
#define O_W22L 21248
#define O_WFH  22016
#define O_WFL  25472
#define O_SC   28928   /* f32[544] */
#define BI_B02 0
#define BI_B11 32
#define BI_B12 64
#define BI_B45 96
#define BI_B22 128
#define BI_BF  144
#define SC_W0P 216
#define SC_W1P 344
#define SC_PREA 472
#define SC_PREC 504
#define SC_PCNI 536
#define O_HHI  31104   /* u32[128*17] */
#define O_HLO  39808
#define O_XR   48512   /* f32[128*33] */
#define O_OUT  65408   /* f32[4 warps][32*67] */
#define SMEM_BYTES (O_OUT + 4*32*67*4)

__global__ __launch_bounds__(NTHR) void ppf_mma_kernel(
    const float* __restrict__ pc, const float* __restrict__ nrm,
    const float* __restrict__ dist,
    const float* __restrict__ w0,  const float* __restrict__ w1,
    const float* __restrict__ b02, const float* __restrict__ b11, const float* __restrict__ b12,
    const float* __restrict__ b20, const float* __restrict__ b21, const float* __restrict__ b22,
    const float* __restrict__ bf,  float* __restrict__ out)
{
    extern __shared__ char smc[];
    float* BS = (float*)(smc + O_SC);
    const int tid = threadIdx.x, lane = tid & 31, w = tid >> 5;
    const int i = blockIdx.y, bx = blockIdx.x;

    // ---- stage weights (dense [N][K] -> pitched) ----
    for (int idx = tid; idx < 1024; idx += NTHR) {
        int n = idx >> 5, k = idx & 31, o = n * P32 + k;
        ((__nv_bfloat16*)(smc + O_W02H))[o] = g_w02h[idx];
        ((__nv_bfloat16*)(smc + O_W02L))[o] = g_w02l[idx];
        ((__nv_bfloat16*)(smc + O_W11H))[o] = g_w11h[idx];
        ((__nv_bfloat16*)(smc + O_W11L))[o] = g_w11l[idx];
        ((__nv_bfloat16*)(smc + O_W12H))[o] = g_w12h[idx];
        ((__nv_bfloat16*)(smc + O_W12L))[o] = g_w12l[idx];
        ((__nv_bfloat16*)(smc + O_W45H))[o] = g_w45h[idx];
        ((__nv_bfloat16*)(smc + O_W45L))[o] = g_w45l[idx];
    }
    for (int idx = tid; idx < 256; idx += NTHR) {
        int n = idx >> 4, k = idx & 15, o = n * P16 + k;
        ((__nv_bfloat16*)(smc + O_W22H))[o] = g_w22h[idx];
        ((__nv_bfloat16*)(smc + O_W22L))[o] = g_w22l[idx];
    }
    for (int idx = tid; idx < 1152; idx += NTHR) {
        int n = idx >> 4, k = idx & 15, o = n * P16 + k;
        ((__nv_bfloat16*)(smc + O_WFH))[o] = g_wfh[idx];
        ((__nv_bfloat16*)(smc + O_WFL))[o] = g_wfl[idx];
    }
    if (tid < 32) {
        BS[BI_B02+tid] = b02[tid];
        BS[BI_B11+tid] = b11[tid];
        BS[BI_B12+tid] = b12[tid];
        BS[BI_B45+tid] = (tid < 16) ? b20[tid] : b21[tid-16];
        BS[SC_PREA+tid] = g_preA[i*32+tid];
        BS[SC_PREC+tid] = g_preC[i*32+tid];
    } else if (tid < 48) {
        int t = tid - 32;
        if (t < 16) BS[BI_B22+t] = b22[t];
    } else if (tid < 54) {
        int t = tid - 48;
        BS[SC_PCNI+t] = (t < 3) ? pc[i*3+t] : nrm[i*3+(t-3)];
    }
    for (int idx = tid; idx < 72; idx += NTHR) BS[BI_BF+idx] = (idx < 66) ? bf[idx] : 0.f;
    for (int idx = tid; idx < 128; idx += NTHR) {
        int r = idx >> 5, c = idx & 31;
        BS[SC_W0P+idx] = w0[(80+r)*32 + c];
        BS[SC_W1P+idx] = w1[(80+r)*32 + c];
    }
    __syncthreads();

    const float pix = BS[SC_PCNI+0], piy = BS[SC_PCNI+1], piz = BS[SC_PCNI+2];
    const float nix = BS[SC_PCNI+3], niy = BS[SC_PCNI+4], niz = BS[SC_PCNI+5];

    for (int jt = 0; jt < 4; jt++) {
        const int j = bx*512 + jt*128 + tid;
        // ---- scalar front: ppf + layer-0 linear parts ----
        float pv[4];
        {
            float pjx = pc[j*3+0], pjy = pc[j*3+1], pjz = pc[j*3+2];
            float njx = nrm[j*3+0], njy = nrm[j*3+1], njz = nrm[j*3+2];
            float d = dist[(size_t)i*NPTS + j];
            float inv = 1.f / (d + EPSV);
            float x0 = (pix-pjx)*inv, x1v = (piy-pjy)*inv, x2v = (piz-pjz)*inv;
            pv[0] = nix*x0 + niy*x1v + niz*x2v;
            pv[1] = njx*x0 + njy*x1v + njz*x2v;
            pv[2] = nix*njx + niy*njy + niz*njz;
            pv[3] = d;
        }
        float xr[32], h[32];
        {
            const float4* pB = (const float4*)(g_preB + (size_t)j*32);
            const float4* pD = (const float4*)(g_preD + (size_t)j*32);
            const float4* pA = (const float4*)(BS + SC_PREA);
            const float4* pC = (const float4*)(BS + SC_PREC);
#pragma unroll
            for (int q = 0; q < 8; q++) {
                float4 vb = __ldg(pB+q), vd = __ldg(pD+q), va = pA[q], vc = pC[q];
                xr[4*q+0]=va.x+vb.x; xr[4*q+1]=va.y+vb.y; xr[4*q+2]=va.z+vb.z; xr[4*q+3]=va.w+vb.w;
                h[4*q+0]=vc.x+vd.x;  h[4*q+1]=vc.y+vd.y;  h[4*q+2]=vc.z+vd.z;  h[4*q+3]=vc.w+vd.w;
            }
#pragma unroll
            for (int r = 0; r < 4; r++) {
                float p = pv[r];
                const float4* a4 = (const float4*)(BS + SC_W0P + r*32);
                const float4* b4 = (const float4*)(BS + SC_W1P + r*32);
#pragma unroll
                for (int q = 0; q < 8; q++) {
                    float4 a = a4[q], b = b4[q];
                    xr[4*q+0]+=p*a.x; xr[4*q+1]+=p*a.y; xr[4*q+2]+=p*a.z; xr[4*q+3]+=p*a.w;
                    h[4*q+0]+=p*b.x;  h[4*q+1]+=p*b.y;  h[4*q+2]+=p*b.z;  h[4*q+3]+=p*b.w;
                }
            }
#pragma unroll
            for (int c = 0; c < 32; c++) h[c] = fmaxf(h[c], 0.f);
        }
        // stage relu(h) hi/lo and xr — warp-local rows
        {
            uint32_t* HH = (uint32_t*)(smc + O_HHI) + tid*17;
            uint32_t* HL = (uint32_t*)(smc + O_HLO) + tid*17;
            float* XP = (float*)(smc + O_XR) + tid*33;
#pragma unroll
            for (int q = 0; q < 16; q++) {
                uint32_t hh = cvt2bf(h[2*q+1], h[2*q]);
                HH[q] = hh;
                HL[q] = lo_resid(hh, h[2*q], h[2*q+1]);
            }
#pragma unroll
            for (int c = 0; c < 32; c++) XP[c] = xr[c];
        }
        __syncwarp();

        const int q0 = lane & 3;
        // ---- both 16-row tiles, weights shared via dual GEMM ----
        uint32_t ah[2][2][4], al[2][2][4];
        int r0[2], r1[2];
        {
            const uint32_t* HHb = (const uint32_t*)(smc + O_HHI);
            const uint32_t* HLb = (const uint32_t*)(smc + O_HLO);
#pragma unroll
            for (int hh = 0; hh < 2; hh++) {
                r0[hh] = w*32 + hh*16 + (lane >> 2);
                r1[hh] = r0[hh] + 8;
#pragma unroll
                for (int kb = 0; kb < 2; kb++) {
                    ah[hh][kb][0] = HHb[r0[hh]*17 + kb*8 + q0];
                    ah[hh][kb][1] = HHb[r1[hh]*17 + kb*8 + q0];
                    ah[hh][kb][2] = HHb[r0[hh]*17 + kb*8 + 4 + q0];
                    ah[hh][kb][3] = HHb[r1[hh]*17 + kb*8 + 4 + q0];
                    al[hh][kb][0] = HLb[r0[hh]*17 + kb*8 + q0];
                    al[hh][kb][1] = HLb[r1[hh]*17 + kb*8 + q0];
                    al[hh][kb][2] = HLb[r0[hh]*17 + kb*8 + 4 + q0];
                    al[hh][kb][3] = HLb[r1[hh]*17 + kb*8 + 4 + q0];
                }
            }
        }
        float c[2][4][4], x1[2][4][4];
        // L1: x1 = relu(h)@W02 + b02 + xr
        gemm_mma_dual<4,2,P32>(c[0], c[1], ah[0], al[0], ah[1], al[1],
                               smc+O_W02H, smc+O_W02L, lane);
        {
            const float* XRb = (const float*)(smc + O_XR);
#pragma unroll
            for (int hh = 0; hh < 2; hh++)
#pragma unroll
            for (int nt = 0; nt < 4; nt++) {
                int col = nt*8 + q0*2;
                float bA = BS[BI_B02+col], bB = BS[BI_B02+col+1];
                x1[hh][nt][0] = c[hh][nt][0] + bA + XRb[r0[hh]*33+col];
                x1[hh][nt][1] = c[hh][nt][1] + bB + XRb[r0[hh]*33+col+1];
                x1[hh][nt][2] = c[hh][nt][2] + bA + XRb[r1[hh]*33+col];
                x1[hh][nt][3] = c[hh][nt][3] + bB + XRb[r1[hh]*33+col+1];
            }
        }
#pragma unroll
        for (int hh = 0; hh < 2; hh++) {
            cvt_frag(ah[hh][0], al[hh][0], x1[hh][0], x1[hh][1]);
            cvt_frag(ah[hh][1], al[hh][1], x1[hh][2], x1[hh][3]);
        }
        // L2: h2 = relu(x1@W11 + b11)
        gemm_mma_dual<4,2,P32>(c[0], c[1], ah[0], al[0], ah[1], al[1],
                               smc+O_W11H, smc+O_W11L, lane);
#pragma unroll
        for (int hh = 0; hh < 2; hh++)
#pragma unroll
        for (int nt = 0; nt < 4; nt++) {
            int col = nt*8 + q0*2;
            float bA = BS[BI_B11+col], bB = BS[BI_B11+col+1];
            c[hh][nt][0] = fmaxf(c[hh][nt][0]+bA, 0.f);
            c[hh][nt][1] = fmaxf(c[hh][nt][1]+bB, 0.f);
            c[hh][nt][2] = fmaxf(c[hh][nt][2]+bA, 0.f);
            c[hh][nt][3] = fmaxf(c[hh][nt][3]+bB, 0.f);
        }
#pragma unroll
        for (int hh = 0; hh < 2; hh++) {
            cvt_frag(ah[hh][0], al[hh][0], c[hh][0], c[hh][1]);
            cvt_frag(ah[hh][1], al[hh][1], c[hh][2], c[hh][3]);
        }
        // L3: x2 = h2@W12 + b12 + x1  (into x1)
        gemm_mma_dual<4,2,P32>(c[0], c[1], ah[0], al[0], ah[1], al[1],
                               smc+O_W12H, smc+O_W12L, lane);
#pragma unroll
        for (int hh = 0; hh < 2; hh++)
#pragma unroll
        for (int nt = 0; nt < 4; nt++) {
            int col = nt*8 + q0*2;
            float bA = BS[BI_B12+col], bB = BS[BI_B12+col+1];
            x1[hh][nt][0] += c[hh][nt][0] + bA;
            x1[hh][nt][1] += c[hh][nt][1] + bB;
            x1[hh][nt][2] += c[hh][nt][2] + bA;
            x1[hh][nt][3] += c[hh][nt][3] + bB;
        }
#pragma unroll
        for (int hh = 0; hh < 2; hh++) {
            cvt_frag(ah[hh][0], al[hh][0], x1[hh][0], x1[hh][1]);
            cvt_frag(ah[hh][1], al[hh][1], x1[hh][2], x1[hh][3]);
        }
        // L4: [R|H] = x2 @ [W20|W21]
        gemm_mma_dual<4,2,P32>(c[0], c[1], ah[0], al[0], ah[1], al[1],
                               smc+O_W45H, smc+O_W45L, lane);
        float R[2][2][4];
#pragma unroll
        for (int hh = 0; hh < 2; hh++)
#pragma unroll
        for (int t = 0; t < 2; t++) {
            int col = t*8 + q0*2;
            float bA = BS[BI_B45+col], bB = BS[BI_B45+col+1];
            R[hh][t][0] = c[hh][t][0]+bA; R[hh][t][1] = c[hh][t][1]+bB;
            R[hh][t][2] = c[hh][t][2]+bA; R[hh][t][3] = c[hh][t][3]+bB;
            float hA = BS[BI_B45+16+col], hB = BS[BI_B45+16+col+1];
            c[hh][2+t][0] = fmaxf(c[hh][2+t][0]+hA, 0.f);
            c[hh][2+t][1] = fmaxf(c[hh][2+t][1]+hB, 0.f);
            c[hh][2+t][2] = fmaxf(c[hh][2+t][2]+hA, 0.f);
            c[hh][2+t][3] = fmaxf(c[hh][2+t][3]+hB, 0.f);
        }
        // L5: x3 = relu(H)@W22 + b22 + R
#pragma unroll
        for (int hh = 0; hh < 2; hh++)
            cvt_frag(ah[hh][0], al[hh][0], c[hh][2], c[hh][3]);
        float c2[2][2][4];
        gemm_mma_dual<2,1,P16>(c2[0], c2[1], ah[0], al[0], ah[1], al[1],
                               smc+O_W22H, smc+O_W22L, lane);
#pragma unroll
        for (int hh = 0; hh < 2; hh++)
#pragma unroll
        for (int t = 0; t < 2; t++) {
            int col = t*8 + q0*2;
            float bA = BS[BI_B22+col], bB = BS[BI_B22+col+1];
            R[hh][t][0] += c2[hh][t][0]+bA; R[hh][t][1] += c2[hh][t][1]+bB;
            R[hh][t][2] += c2[hh][t][2]+bA; R[hh][t][3] += c2[hh][t][3]+bB;
        }
        // L6 dual: out = x3 @ WF (+bf) for both tiles with one weight pass
#pragma unroll
        for (int hh = 0; hh < 2; hh++)
            cvt_frag(ah[hh][0], al[hh][0], R[hh][0], R[hh][1]);
        float cf[2][9][4];
        gemm_mma_dual<9,1,P16>(cf[0], cf[1], ah[0], al[0], ah[1], al[1],
                               smc+O_WFH, smc+O_WFL, lane);
        float* so = (float*)(smc + O_OUT) + w*(32*67);
        const int sr = lane >> 2;
#pragma unroll
        for (int hh = 0; hh < 2; hh++) {
            int s0 = hh*16 + sr, s1 = s0 + 8;
#pragma unroll
            for (int nt = 0; nt < 9; nt++) {
                int col = nt*8 + q0*2;
                if (col < 66) {
                    float b = BS[BI_BF+col];
                    so[s0*67+col] = cf[hh][nt][0]+b;
                    so[s1*67+col] = cf[hh][nt][2]+b;
                }
                if (col+1 < 66) {
                    float b = BS[BI_BF+col+1];
                    so[s0*67+col+1] = cf[hh][nt][1]+b;
                    so[s1*67+col+1] = cf[hh][nt][3]+b;
                }
            }
        }
        __syncwarp();
        // coalesced flush: 32 rows * 66 = 2112 contiguous floats per warp
        size_t gbase = ((size_t)i*NPTS + (size_t)bx*512 + jt*128 + w*32) * 66;
#pragma unroll 6
        for (int s = 0; s < 66; s++) {
            int idx = s*32 + lane;
            int jj = idx / 66, cc = idx - jj*66;
            out[gbase + idx] = so[jj*67 + cc];
        }
        __syncwarp();
    }
}

extern "C" void kernel_launch(void* const* d_in, const int* in_sizes, int n_in,
                              void* d_out, int out_size) {
    const float* pc   = (const float*)d_in[0];
    const float* nrm  = (const float*)d_in[1];
    const float* dist = (const float*)d_in[2];
    const float* feat = (const float*)d_in[3];
    const float* w0   = (const float*)d_in[4];
    const float* b0   = (const float*)d_in[5];
    const float* w1   = (const float*)d_in[6];
    const float* b1   = (const float*)d_in[7];
    const float* w02  = (const float*)d_in[8];
    const float* b02  = (const float*)d_in[9];
    const float* w11  = (const float*)d_in[10];
    const float* b11  = (const float*)d_in[11];
    const float* w12  = (const float*)d_in[12];
    const float* b12  = (const float*)d_in[13];
    const float* w20  = (const float*)d_in[14];
    const float* b20  = (const float*)d_in[15];
    const float* w21  = (const float*)d_in[16];
    const float* b21  = (const float*)d_in[17];
    const float* w22  = (const float*)d_in[18];
    const float* b22  = (const float*)d_in[19];
    const float* wf   = (const float*)d_in[20];
    const float* bf   = (const float*)d_in[21];
    float* out = (float*)d_out;

    cudaFuncSetAttribute(ppf_mma_kernel, cudaFuncAttributeMaxDynamicSharedMemorySize, SMEM_BYTES);

    prep_all<<<272, NTHR>>>(feat, w0, b0, w1, b1, w02, w11, w12, w20, w21, w22, wf);

    dim3 grid(2, NPTS);
    ppf_mma_kernel<<<grid, NTHR, SMEM_BYTES>>>(
        pc, nrm, dist, w0, w1,
        b02, b11, b12, b20, b21, b22, bf, out);
}